// round 1
// baseline (speedup 1.0000x reference)
#include <cuda_runtime.h>
#include <math.h>

#define BB 32
#define SS 512
#define DD 768
#define PP 256
#define HH 12
#define DH 64
#define DFF 3072
#define EPS_LN 1e-5f
#define EPS_TRIP 1e-6f

// ---------------- scratch (no allocations allowed) ----------------
__device__ float g_mem[PP * 2 * DD];     // [P,2,D] (cls, s_emb)
__device__ float g_sE[PP * DD];
__device__ float g_pE[PP * DD];
__device__ float g_nE[PP * DD];
__device__ float g_K[PP * 2 * DD];
__device__ float g_V[PP * 2 * DD];
__device__ float g_q[PP * DD];
__device__ float g_o[PP * DD];
__device__ float g_ao[PP * DD];
__device__ float g_h[PP * DD];
__device__ float g_f1[PP * DFF];
__device__ float g_f2[PP * DD];
__device__ float g_ap[PP * DD];
__device__ float g_an[PP * DD];
__device__ float g_pl[PP];

// ---------------- block reduce helper ----------------
__device__ __forceinline__ float block_reduce_sum(float v, float* sh) {
    int lane = threadIdx.x & 31;
    int w = threadIdx.x >> 5;
    #pragma unroll
    for (int o = 16; o > 0; o >>= 1) v += __shfl_down_sync(0xffffffffu, v, o);
    __syncthreads();
    if (lane == 0) sh[w] = v;
    __syncthreads();
    int nw = blockDim.x >> 5;
    float r = (threadIdx.x < nw) ? sh[threadIdx.x] : 0.f;
    if (w == 0) {
        #pragma unroll
        for (int o = 16; o > 0; o >>= 1) r += __shfl_down_sync(0xffffffffu, r, o);
        if (lane == 0) sh[0] = r;
    }
    __syncthreads();
    return sh[0];
}

// ---------------- pooling: build mem, s/p/n embeddings ----------------
__global__ void pool_kernel(const float* __restrict__ se, const int* __restrict__ sidx,
                            const int* __restrict__ ss, const int* __restrict__ ps,
                            const int* __restrict__ ns) {
    int p = blockIdx.x;
    const float* base = se + (size_t)sidx[p] * SS * DD;
    int t = threadIdx.x;
    int s0 = ss[2 * p], s1 = ss[2 * p + 1];
    int p0 = ps[2 * p], p1 = ps[2 * p + 1];
    int n0 = ns[2 * p], n1 = ns[2 * p + 1];
    float inv_s = 1.0f / (float)(s1 - s0);
    float inv_p = 1.0f / (float)(p1 - p0);
    float inv_n = 1.0f / (float)(n1 - n0);
    #pragma unroll
    for (int i = 0; i < 3; i++) {
        int d = t + i * 256;
        float as = 0.f, ap = 0.f, an = 0.f;
        for (int r = s0; r < s1; r++) as += base[r * DD + d];
        for (int r = p0; r < p1; r++) ap += base[r * DD + d];
        for (int r = n0; r < n1; r++) an += base[r * DD + d];
        as *= inv_s; ap *= inv_p; an *= inv_n;
        g_sE[p * DD + d] = as;
        g_pE[p * DD + d] = ap;
        g_nE[p * DD + d] = an;
        g_mem[p * 2 * DD + d] = base[d];          // cls (row 0)
        g_mem[p * 2 * DD + DD + d] = as;          // s_emb
    }
}

// ---------------- tiled SGEMM: C[M,N] = A[M,K] @ W[K,N] + bias (opt ReLU) ----------------
#define GT 64
#define GKT 16
template <bool RELU>
__global__ __launch_bounds__(256) void gemm_kernel(
    const float* __restrict__ A, const float* __restrict__ W,
    const float* __restrict__ bias, float* __restrict__ C,
    int M, int K, int N) {
    __shared__ float As[GKT][GT + 1];
    __shared__ float Bs[GKT][GT + 1];
    int tid = threadIdx.x;
    int tx = tid & 15;
    int ty = tid >> 4;
    int row0 = blockIdx.y * GT;
    int col0 = blockIdx.x * GT;
    float acc[4][4] = {};
    for (int kt = 0; kt < K; kt += GKT) {
        #pragma unroll
        for (int i = 0; i < 4; i++) {
            int idx = tid + i * 256;
            int m = idx >> 4;          // /16
            int k = idx & 15;
            As[k][m] = A[(size_t)(row0 + m) * K + kt + k];
        }
        #pragma unroll
        for (int i = 0; i < 4; i++) {
            int idx = tid + i * 256;
            int k = idx >> 6;          // /64
            int n = idx & 63;
            Bs[k][n] = W[(size_t)(kt + k) * N + col0 + n];
        }
        __syncthreads();
        #pragma unroll
        for (int k = 0; k < GKT; k++) {
            float a[4], b[4];
            #pragma unroll
            for (int i = 0; i < 4; i++) a[i] = As[k][ty * 4 + i];
            #pragma unroll
            for (int j = 0; j < 4; j++) b[j] = Bs[k][tx * 4 + j];
            #pragma unroll
            for (int i = 0; i < 4; i++)
                #pragma unroll
                for (int j = 0; j < 4; j++)
                    acc[i][j] = fmaf(a[i], b[j], acc[i][j]);
        }
        __syncthreads();
    }
    #pragma unroll
    for (int i = 0; i < 4; i++) {
        int r = row0 + ty * 4 + i;
        #pragma unroll
        for (int j = 0; j < 4; j++) {
            int c = col0 + tx * 4 + j;
            float v = acc[i][j] + bias[c];
            if (RELU) v = fmaxf(v, 0.f);
            C[(size_t)r * N + c] = v;
        }
    }
}

// ---------------- 2-slot attention per (pair, head) ----------------
__global__ void attn_kernel(const float* __restrict__ q, const float* __restrict__ Kb,
                            const float* __restrict__ Vb, float* __restrict__ o) {
    int ph = blockIdx.x;
    int p = ph / HH;
    int h = ph % HH;
    int d = threadIdx.x;  // 0..63
    size_t qoff = (size_t)p * DD + h * DH + d;
    size_t k0off = (size_t)p * 2 * DD + h * DH + d;
    float qd = q[qoff];
    float s0 = qd * Kb[k0off];
    float s1 = qd * Kb[k0off + DD];
    __shared__ float sh[4];
    #pragma unroll
    for (int off = 16; off > 0; off >>= 1) {
        s0 += __shfl_down_sync(0xffffffffu, s0, off);
        s1 += __shfl_down_sync(0xffffffffu, s1, off);
    }
    int w = threadIdx.x >> 5;
    if ((threadIdx.x & 31) == 0) { sh[w * 2] = s0; sh[w * 2 + 1] = s1; }
    __syncthreads();
    s0 = (sh[0] + sh[2]) * 0.125f;  // 1/sqrt(64)
    s1 = (sh[1] + sh[3]) * 0.125f;
    float m = fmaxf(s0, s1);
    float e0 = expf(s0 - m), e1 = expf(s1 - m);
    float inv = 1.f / (e0 + e1);
    float a0 = e0 * inv, a1 = e1 * inv;
    o[qoff] = a0 * Vb[k0off] + a1 * Vb[k0off + DD];
}

// ---------------- residual add + LayerNorm ----------------
__global__ void add_ln_kernel(const float* __restrict__ x, const float* __restrict__ r,
                              const float* __restrict__ g, const float* __restrict__ b,
                              float* __restrict__ out) {
    int p = blockIdx.x;
    int t = threadIdx.x;  // 256
    __shared__ float sh[8];
    float v[3];
    float s = 0.f, s2 = 0.f;
    #pragma unroll
    for (int i = 0; i < 3; i++) {
        int d = t + i * 256;
        v[i] = x[(size_t)p * DD + d] + r[(size_t)p * DD + d];
        s += v[i];
        s2 += v[i] * v[i];
    }
    float sum = block_reduce_sum(s, sh);
    float sumsq = block_reduce_sum(s2, sh);
    float mean = sum * (1.0f / DD);
    float var = sumsq * (1.0f / DD) - mean * mean;
    float rstd = rsqrtf(var + EPS_LN);
    #pragma unroll
    for (int i = 0; i < 3; i++) {
        int d = t + i * 256;
        out[(size_t)p * DD + d] = (v[i] - mean) * rstd * g[d] + b[d];
    }
}

// ---------------- triplet loss per pair ----------------
__global__ void loss_kernel(const float* __restrict__ sE, const float* __restrict__ ap,
                            const float* __restrict__ an, float* __restrict__ pl) {
    int p = blockIdx.x;
    int t = threadIdx.x;
    __shared__ float sh[8];
    float sp = 0.f, sn = 0.f;
    #pragma unroll
    for (int i = 0; i < 3; i++) {
        int d = t + i * 256;
        float a = sE[(size_t)p * DD + d] - ap[(size_t)p * DD + d] + EPS_TRIP;
        float b = sE[(size_t)p * DD + d] - an[(size_t)p * DD + d] + EPS_TRIP;
        sp += a * a;
        sn += b * b;
    }
    float SP = block_reduce_sum(sp, sh);
    float SN = block_reduce_sum(sn, sh);
    if (t == 0) pl[p] = fmaxf(sqrtf(SP) - sqrtf(SN) + 1.0f, 0.f);
}

__global__ void reduce_kernel(const float* __restrict__ pl, float* __restrict__ out) {
    int t = threadIdx.x;  // 256 == PP
    __shared__ float sh[8];
    float v = pl[t];
    float s = block_reduce_sum(v, sh);
    if (t == 0) out[0] = s * (1.0f / PP);
}

// ---------------- host launch ----------------
extern "C" void kernel_launch(void* const* d_in, const int* in_sizes, int n_in,
                              void* d_out, int out_size) {
    const float* sent = (const float*)d_in[0];
    const int* sidx = (const int*)d_in[1];
    const int* ss = (const int*)d_in[2];
    const int* ps = (const int*)d_in[3];
    const int* ns = (const int*)d_in[4];
    const float* Wq = (const float*)d_in[5];
    const float* bq = (const float*)d_in[6];
    const float* Wk = (const float*)d_in[7];
    const float* bk = (const float*)d_in[8];
    const float* Wv = (const float*)d_in[9];
    const float* bv = (const float*)d_in[10];
    const float* Wo = (const float*)d_in[11];
    const float* bo = (const float*)d_in[12];
    const float* l1g = (const float*)d_in[13];
    const float* l1b = (const float*)d_in[14];
    const float* l2g = (const float*)d_in[15];
    const float* l2b = (const float*)d_in[16];
    const float* W1 = (const float*)d_in[17];
    const float* b1 = (const float*)d_in[18];
    const float* W2 = (const float*)d_in[19];
    const float* b2 = (const float*)d_in[20];
    float* out = (float*)d_out;

    float *mem, *sE, *pE, *nE, *Kb, *Vb, *qb, *ob, *ao, *hb, *f1, *f2, *apb, *anb, *pl;
    cudaGetSymbolAddress((void**)&mem, g_mem);
    cudaGetSymbolAddress((void**)&sE, g_sE);
    cudaGetSymbolAddress((void**)&pE, g_pE);
    cudaGetSymbolAddress((void**)&nE, g_nE);
    cudaGetSymbolAddress((void**)&Kb, g_K);
    cudaGetSymbolAddress((void**)&Vb, g_V);
    cudaGetSymbolAddress((void**)&qb, g_q);
    cudaGetSymbolAddress((void**)&ob, g_o);
    cudaGetSymbolAddress((void**)&ao, g_ao);
    cudaGetSymbolAddress((void**)&hb, g_h);
    cudaGetSymbolAddress((void**)&f1, g_f1);
    cudaGetSymbolAddress((void**)&f2, g_f2);
    cudaGetSymbolAddress((void**)&apb, g_ap);
    cudaGetSymbolAddress((void**)&anb, g_an);
    cudaGetSymbolAddress((void**)&pl, g_pl);

    pool_kernel<<<PP, 256>>>(sent, sidx, ss, ps, ns);

    // K,V projections of mem (shared by both branches): [2P, D] @ [D, D]
    gemm_kernel<false><<<dim3(DD / GT, 2 * PP / GT), 256>>>(mem, Wk, bk, Kb, 2 * PP, DD, DD);
    gemm_kernel<false><<<dim3(DD / GT, 2 * PP / GT), 256>>>(mem, Wv, bv, Vb, 2 * PP, DD, DD);

    const float* xs[2] = {pE, nE};
    float* outs[2] = {apb, anb};
    for (int br = 0; br < 2; br++) {
        const float* x = xs[br];
        float* att = outs[br];
        gemm_kernel<false><<<dim3(DD / GT, PP / GT), 256>>>(x, Wq, bq, qb, PP, DD, DD);
        attn_kernel<<<PP * HH, 64>>>(qb, Kb, Vb, ob);
        gemm_kernel<false><<<dim3(DD / GT, PP / GT), 256>>>(ob, Wo, bo, ao, PP, DD, DD);
        add_ln_kernel<<<PP, 256>>>(x, ao, l1g, l1b, hb);
        gemm_kernel<true><<<dim3(DFF / GT, PP / GT), 256>>>(hb, W1, b1, f1, PP, DD, DFF);
        gemm_kernel<false><<<dim3(DD / GT, PP / GT), 256>>>(f1, W2, b2, f2, PP, DFF, DD);
        add_ln_kernel<<<PP, 256>>>(hb, f2, l2g, l2b, att);
    }

    loss_kernel<<<PP, 256>>>(sE, apb, anb, pl);
    reduce_kernel<<<1, 256>>>(pl, out);
}

// round 2
// speedup vs baseline: 4.2214x; 4.2214x over previous
#include <cuda_runtime.h>
#include <math.h>

#define SS 512
#define DD 768
#define PP 256
#define HH 12
#define DH 64
#define DFF 3072
#define M2 (2*PP)
#define EPS_LN 1e-5f
#define EPS_TRIP 1e-6f

// ---------------- scratch (no allocations allowed) ----------------
__device__ float g_mem[M2 * DD];      // [P,2,D] (cls, s_emb) = 512 rows
__device__ float g_sE[PP * DD];
__device__ float g_x[M2 * DD];        // rows 0..255 = pE, 256..511 = nE
__device__ float g_K[M2 * DD];
__device__ float g_V[M2 * DD];
__device__ float g_q[M2 * DD];
__device__ float g_o[M2 * DD];
__device__ float g_ao[M2 * DD];
__device__ float g_h[M2 * DD];
__device__ float g_f1[M2 * DFF];
__device__ float g_f2[M2 * DD];
__device__ float g_att[M2 * DD];
__device__ float g_pl[PP];

// ---------------- helpers ----------------
__device__ __forceinline__ float tf32r(float f) {
    unsigned r;
    asm("cvt.rna.tf32.f32 %0, %1;" : "=r"(r) : "f"(f));
    return __uint_as_float(r);
}

__device__ __forceinline__ void mma_tf32(float* c, const unsigned* a, unsigned b0, unsigned b1) {
    asm volatile(
        "mma.sync.aligned.m16n8k8.row.col.f32.tf32.tf32.f32 "
        "{%0,%1,%2,%3}, {%4,%5,%6,%7}, {%8,%9}, {%0,%1,%2,%3};"
        : "+f"(c[0]), "+f"(c[1]), "+f"(c[2]), "+f"(c[3])
        : "r"(a[0]), "r"(a[1]), "r"(a[2]), "r"(a[3]), "r"(b0), "r"(b1));
}

__device__ __forceinline__ float block_reduce_sum(float v, float* sh) {
    int lane = threadIdx.x & 31;
    int w = threadIdx.x >> 5;
    #pragma unroll
    for (int o = 16; o > 0; o >>= 1) v += __shfl_down_sync(0xffffffffu, v, o);
    __syncthreads();
    if (lane == 0) sh[w] = v;
    __syncthreads();
    int nw = blockDim.x >> 5;
    float r = (threadIdx.x < nw) ? sh[threadIdx.x] : 0.f;
    if (w == 0) {
        #pragma unroll
        for (int o = 16; o > 0; o >>= 1) r += __shfl_down_sync(0xffffffffu, r, o);
        if (lane == 0) sh[0] = r;
    }
    __syncthreads();
    return sh[0];
}

// ---------------- pooling ----------------
__global__ void pool_kernel(const float* __restrict__ se, const int* __restrict__ sidx,
                            const int* __restrict__ ss, const int* __restrict__ ps,
                            const int* __restrict__ ns) {
    int p = blockIdx.x;
    const float* base = se + (size_t)sidx[p] * SS * DD;
    int t = threadIdx.x;
    int s0 = ss[2 * p], s1 = ss[2 * p + 1];
    int p0 = ps[2 * p], p1 = ps[2 * p + 1];
    int n0 = ns[2 * p], n1 = ns[2 * p + 1];
    float inv_s = 1.0f / (float)(s1 - s0);
    float inv_p = 1.0f / (float)(p1 - p0);
    float inv_n = 1.0f / (float)(n1 - n0);
    #pragma unroll
    for (int i = 0; i < 3; i++) {
        int d = t + i * 256;
        float as = 0.f, ap = 0.f, an = 0.f;
        for (int r = s0; r < s1; r++) as += base[r * DD + d];
        for (int r = p0; r < p1; r++) ap += base[r * DD + d];
        for (int r = n0; r < n1; r++) an += base[r * DD + d];
        as *= inv_s; ap *= inv_p; an *= inv_n;
        g_sE[p * DD + d] = as;
        g_x[p * DD + d] = ap;
        g_x[(p + PP) * DD + d] = an;
        g_mem[p * 2 * DD + d] = base[d];
        g_mem[p * 2 * DD + DD + d] = as;
    }
}

// ---------------- TF32 tensor-core GEMM ----------------
// C[M,N] = A[M,K] @ W[K,N] + bias, optional ReLU.
// BM=64, BK=32, BN template (64 or 128). 256 threads = 8 warps (2m x 4n).
template <int BN, bool RELU>
__global__ __launch_bounds__(256) void tgemm(
    const float* __restrict__ A, const float* __restrict__ W,
    const float* __restrict__ bias, float* __restrict__ C,
    int M, int K, int N) {
    constexpr int BM = 64, BK = 32;
    constexpr int SAS = BK + 4;          // sA stride (floats)
    constexpr int SBS = BN + 4;          // sB stride
    constexpr int NT = BN / 32;          // n-tiles (8-wide) per warp
    constexpr int NB = (BK * BN / 4) / 256;  // float4 B loads per thread

    __shared__ float sA[BM * SAS];
    __shared__ float sB[BK * SBS];

    int tid = threadIdx.x;
    int lane = tid & 31;
    int wid = tid >> 5;
    int wm = wid >> 2;                   // 0..1
    int wn = wid & 3;                    // 0..3
    int q = lane >> 2;                   // 0..7
    int r4 = lane & 3;                   // 0..3
    int row0 = blockIdx.y * BM;
    int col0 = blockIdx.x * BN;

    float acc[2][NT][4];
    #pragma unroll
    for (int i = 0; i < 2; i++)
        #pragma unroll
        for (int j = 0; j < NT; j++)
            #pragma unroll
            for (int k = 0; k < 4; k++) acc[i][j][k] = 0.f;

    // A: 2 float4 per thread; B: NB float4 per thread
    int arow0 = tid >> 3;
    int acol = (tid & 7) * 4;
    const float* Ag = A + (size_t)row0 * K;
    const float* Bg = W + col0;

    float4 pa[2], pb[NB];

    auto loadg = [&](int k0) {
        pa[0] = *(const float4*)(Ag + (size_t)arow0 * K + k0 + acol);
        pa[1] = *(const float4*)(Ag + (size_t)(arow0 + 32) * K + k0 + acol);
        #pragma unroll
        for (int i = 0; i < NB; i++) {
            int idx = tid + i * 256;
            int br = idx / (BN / 4);
            int bc = (idx % (BN / 4)) * 4;
            pb[i] = *(const float4*)(Bg + (size_t)(k0 + br) * N + bc);
        }
    };
    auto stores = [&]() {
        #pragma unroll
        for (int i = 0; i < 2; i++) {
            float4 v = pa[i];
            float4 w4 = make_float4(tf32r(v.x), tf32r(v.y), tf32r(v.z), tf32r(v.w));
            *(float4*)&sA[(arow0 + i * 32) * SAS + acol] = w4;
        }
        #pragma unroll
        for (int i = 0; i < NB; i++) {
            int idx = tid + i * 256;
            int br = idx / (BN / 4);
            int bc = (idx % (BN / 4)) * 4;
            float4 v = pb[i];
            float4 w4 = make_float4(tf32r(v.x), tf32r(v.y), tf32r(v.z), tf32r(v.w));
            *(float4*)&sB[br * SBS + bc] = w4;
        }
    };
    auto compute = [&]() {
        #pragma unroll
        for (int ks = 0; ks < 4; ks++) {
            int kk = ks * 8;
            unsigned a[2][4];
            #pragma unroll
            for (int mt = 0; mt < 2; mt++) {
                int rr = wm * 32 + mt * 16 + q;
                a[mt][0] = __float_as_uint(sA[rr * SAS + kk + r4]);
                a[mt][1] = __float_as_uint(sA[(rr + 8) * SAS + kk + r4]);
                a[mt][2] = __float_as_uint(sA[rr * SAS + kk + r4 + 4]);
                a[mt][3] = __float_as_uint(sA[(rr + 8) * SAS + kk + r4 + 4]);
            }
            #pragma unroll
            for (int nt = 0; nt < NT; nt++) {
                int cc = wn * (BN / 4) + nt * 8 + q;
                unsigned b0 = __float_as_uint(sB[(kk + r4) * SBS + cc]);
                unsigned b1 = __float_as_uint(sB[(kk + 4 + r4) * SBS + cc]);
                mma_tf32(acc[0][nt], a[0], b0, b1);
                mma_tf32(acc[1][nt], a[1], b0, b1);
            }
        }
    };

    int niter = K / BK;
    loadg(0);
    stores();
    __syncthreads();
    for (int it = 0; it < niter; it++) {
        if (it + 1 < niter) loadg((it + 1) * BK);
        compute();
        __syncthreads();
        if (it + 1 < niter) {
            stores();
            __syncthreads();
        }
    }

    // epilogue
    #pragma unroll
    for (int mt = 0; mt < 2; mt++) {
        int rr = row0 + wm * 32 + mt * 16 + q;
        #pragma unroll
        for (int nt = 0; nt < NT; nt++) {
            int cc = col0 + wn * (BN / 4) + nt * 8 + 2 * r4;
            float b0 = bias[cc], b1 = bias[cc + 1];
            float v0 = acc[mt][nt][0] + b0;
            float v1 = acc[mt][nt][1] + b1;
            float v2 = acc[mt][nt][2] + b0;
            float v3 = acc[mt][nt][3] + b1;
            if (RELU) {
                v0 = fmaxf(v0, 0.f); v1 = fmaxf(v1, 0.f);
                v2 = fmaxf(v2, 0.f); v3 = fmaxf(v3, 0.f);
            }
            *(float2*)&C[(size_t)rr * N + cc] = make_float2(v0, v1);
            *(float2*)&C[(size_t)(rr + 8) * N + cc] = make_float2(v2, v3);
        }
    }
}

// ---------------- 2-slot attention (batched rows 0..511) ----------------
__global__ void attn_kernel(const float* __restrict__ q, const float* __restrict__ Kb,
                            const float* __restrict__ Vb, float* __restrict__ o) {
    int rh = blockIdx.x;
    int r = rh / HH;
    int h = rh % HH;
    int p = r & (PP - 1);
    int d = threadIdx.x;
    size_t qoff = (size_t)r * DD + h * DH + d;
    size_t k0off = (size_t)p * 2 * DD + h * DH + d;
    float qd = q[qoff];
    float s0 = qd * Kb[k0off];
    float s1 = qd * Kb[k0off + DD];
    __shared__ float sh[4];
    #pragma unroll
    for (int off = 16; off > 0; off >>= 1) {
        s0 += __shfl_down_sync(0xffffffffu, s0, off);
        s1 += __shfl_down_sync(0xffffffffu, s1, off);
    }
    int w = threadIdx.x >> 5;
    if ((threadIdx.x & 31) == 0) { sh[w * 2] = s0; sh[w * 2 + 1] = s1; }
    __syncthreads();
    s0 = (sh[0] + sh[2]) * 0.125f;
    s1 = (sh[1] + sh[3]) * 0.125f;
    float m = fmaxf(s0, s1);
    float e0 = expf(s0 - m), e1 = expf(s1 - m);
    float inv = 1.f / (e0 + e1);
    o[qoff] = (e0 * inv) * Vb[k0off] + (e1 * inv) * Vb[k0off + DD];
}

// ---------------- residual add + LayerNorm ----------------
__global__ void add_ln_kernel(const float* __restrict__ x, const float* __restrict__ r,
                              const float* __restrict__ g, const float* __restrict__ b,
                              float* __restrict__ out) {
    int p = blockIdx.x;
    int t = threadIdx.x;
    __shared__ float sh[8];
    float v[3];
    float s = 0.f, s2 = 0.f;
    #pragma unroll
    for (int i = 0; i < 3; i++) {
        int d = t + i * 256;
        v[i] = x[(size_t)p * DD + d] + r[(size_t)p * DD + d];
        s += v[i];
        s2 += v[i] * v[i];
    }
    float sum = block_reduce_sum(s, sh);
    float sumsq = block_reduce_sum(s2, sh);
    float mean = sum * (1.0f / DD);
    float var = sumsq * (1.0f / DD) - mean * mean;
    float rstd = rsqrtf(var + EPS_LN);
    #pragma unroll
    for (int i = 0; i < 3; i++) {
        int d = t + i * 256;
        out[(size_t)p * DD + d] = (v[i] - mean) * rstd * g[d] + b[d];
    }
}

// ---------------- triplet loss ----------------
__global__ void loss_kernel(const float* __restrict__ sE, const float* __restrict__ att,
                            float* __restrict__ pl) {
    int p = blockIdx.x;
    int t = threadIdx.x;
    __shared__ float sh[8];
    float sp = 0.f, sn = 0.f;
    #pragma unroll
    for (int i = 0; i < 3; i++) {
        int d = t + i * 256;
        float a = sE[(size_t)p * DD + d] - att[(size_t)p * DD + d] + EPS_TRIP;
        float b = sE[(size_t)p * DD + d] - att[(size_t)(p + PP) * DD + d] + EPS_TRIP;
        sp += a * a;
        sn += b * b;
    }
    float SP = block_reduce_sum(sp, sh);
    float SN = block_reduce_sum(sn, sh);
    if (t == 0) pl[p] = fmaxf(sqrtf(SP) - sqrtf(SN) + 1.0f, 0.f);
}

__global__ void reduce_kernel(const float* __restrict__ pl, float* __restrict__ out) {
    int t = threadIdx.x;
    __shared__ float sh[8];
    float s = block_reduce_sum(pl[t], sh);
    if (t == 0) out[0] = s * (1.0f / PP);
}

// ---------------- host launch ----------------
extern "C" void kernel_launch(void* const* d_in, const int* in_sizes, int n_in,
                              void* d_out, int out_size) {
    const float* sent = (const float*)d_in[0];
    const int* sidx = (const int*)d_in[1];
    const int* ss = (const int*)d_in[2];
    const int* ps = (const int*)d_in[3];
    const int* ns = (const int*)d_in[4];
    const float* Wq = (const float*)d_in[5];
    const float* bq = (const float*)d_in[6];
    const float* Wk = (const float*)d_in[7];
    const float* bk = (const float*)d_in[8];
    const float* Wv = (const float*)d_in[9];
    const float* bv = (const float*)d_in[10];
    const float* Wo = (const float*)d_in[11];
    const float* bo = (const float*)d_in[12];
    const float* l1g = (const float*)d_in[13];
    const float* l1b = (const float*)d_in[14];
    const float* l2g = (const float*)d_in[15];
    const float* l2b = (const float*)d_in[16];
    const float* W1 = (const float*)d_in[17];
    const float* b1 = (const float*)d_in[18];
    const float* W2 = (const float*)d_in[19];
    const float* b2 = (const float*)d_in[20];
    float* out = (float*)d_out;

    float *mem, *sE, *xb, *Kb, *Vb, *qb, *ob, *ao, *hb, *f1, *f2, *att, *pl;
    cudaGetSymbolAddress((void**)&mem, g_mem);
    cudaGetSymbolAddress((void**)&sE, g_sE);
    cudaGetSymbolAddress((void**)&xb, g_x);
    cudaGetSymbolAddress((void**)&Kb, g_K);
    cudaGetSymbolAddress((void**)&Vb, g_V);
    cudaGetSymbolAddress((void**)&qb, g_q);
    cudaGetSymbolAddress((void**)&ob, g_o);
    cudaGetSymbolAddress((void**)&ao, g_ao);
    cudaGetSymbolAddress((void**)&hb, g_h);
    cudaGetSymbolAddress((void**)&f1, g_f1);
    cudaGetSymbolAddress((void**)&f2, g_f2);
    cudaGetSymbolAddress((void**)&att, g_att);
    cudaGetSymbolAddress((void**)&pl, g_pl);

    pool_kernel<<<PP, 256>>>(sent, sidx, ss, ps, ns);

    dim3 gD(DD / 64, M2 / 64);     // 12 x 8 = 96 blocks
    dim3 gF1(DFF / 128, M2 / 64);  // 24 x 8 = 192 blocks

    tgemm<64, false><<<gD, 256>>>(mem, Wk, bk, Kb, M2, DD, DD);
    tgemm<64, false><<<gD, 256>>>(mem, Wv, bv, Vb, M2, DD, DD);
    tgemm<64, false><<<gD, 256>>>(xb, Wq, bq, qb, M2, DD, DD);
    attn_kernel<<<M2 * HH, 64>>>(qb, Kb, Vb, ob);
    tgemm<64, false><<<gD, 256>>>(ob, Wo, bo, ao, M2, DD, DD);
    add_ln_kernel<<<M2, 256>>>(xb, ao, l1g, l1b, hb);
    tgemm<128, true><<<gF1, 256>>>(hb, W1, b1, f1, M2, DD, DFF);
    tgemm<64, false><<<gD, 256>>>(f1, W2, b2, f2, M2, DFF, DD);
    add_ln_kernel<<<M2, 256>>>(hb, f2, l2g, l2b, att);

    loss_kernel<<<PP, 256>>>(sE, att, pl);
    reduce_kernel<<<1, 256>>>(pl, out);
}

// round 3
// speedup vs baseline: 5.8354x; 1.3823x over previous
#include <cuda_runtime.h>
#include <math.h>

#define SS 512
#define DD 768
#define PP 256
#define HH 12
#define DH 64
#define DFF 3072
#define M2 (2*PP)
#define EPS_LN 1e-5f
#define EPS_TRIP 1e-6f

// ---------------- scratch ----------------
__device__ float g_mem[M2 * DD];
__device__ float g_sE[PP * DD];
__device__ float g_x[M2 * DD];
__device__ float g_K[M2 * DD];
__device__ float g_V[M2 * DD];
__device__ float g_q[M2 * DD];
__device__ float g_o[M2 * DD];
__device__ float g_ao[2 * M2 * DD];   // 2 split-K partials
__device__ float g_h[M2 * DD];
__device__ float g_f1[M2 * DFF];
__device__ float g_f2[4 * M2 * DD];   // 4 split-K partials
__device__ float g_att[M2 * DD];
__device__ float g_pl[PP];

// ---------------- helpers ----------------
__device__ __forceinline__ float tf32r(float f) {
    unsigned r;
    asm("cvt.rna.tf32.f32 %0, %1;" : "=r"(r) : "f"(f));
    return __uint_as_float(r);
}

__device__ __forceinline__ void mma_tf32(float* c, const unsigned* a, unsigned b0, unsigned b1) {
    asm volatile(
        "mma.sync.aligned.m16n8k8.row.col.f32.tf32.tf32.f32 "
        "{%0,%1,%2,%3}, {%4,%5,%6,%7}, {%8,%9}, {%0,%1,%2,%3};"
        : "+f"(c[0]), "+f"(c[1]), "+f"(c[2]), "+f"(c[3])
        : "r"(a[0]), "r"(a[1]), "r"(a[2]), "r"(a[3]), "r"(b0), "r"(b1));
}

__device__ __forceinline__ float block_reduce_sum(float v, float* sh) {
    int lane = threadIdx.x & 31;
    int w = threadIdx.x >> 5;
    #pragma unroll
    for (int o = 16; o > 0; o >>= 1) v += __shfl_down_sync(0xffffffffu, v, o);
    __syncthreads();
    if (lane == 0) sh[w] = v;
    __syncthreads();
    int nw = blockDim.x >> 5;
    float r = (threadIdx.x < nw) ? sh[threadIdx.x] : 0.f;
    if (w == 0) {
        #pragma unroll
        for (int o = 16; o > 0; o >>= 1) r += __shfl_down_sync(0xffffffffu, r, o);
        if (lane == 0) sh[0] = r;
    }
    __syncthreads();
    return sh[0];
}

// ---------------- pooling ----------------
__global__ void pool_kernel(const float* __restrict__ se, const int* __restrict__ sidx,
                            const int* __restrict__ ss, const int* __restrict__ ps,
                            const int* __restrict__ ns) {
    int p = blockIdx.x;
    const float* base = se + (size_t)sidx[p] * SS * DD;
    int t = threadIdx.x;
    int s0 = ss[2 * p], s1 = ss[2 * p + 1];
    int p0 = ps[2 * p], p1 = ps[2 * p + 1];
    int n0 = ns[2 * p], n1 = ns[2 * p + 1];
    float inv_s = 1.0f / (float)(s1 - s0);
    float inv_p = 1.0f / (float)(p1 - p0);
    float inv_n = 1.0f / (float)(n1 - n0);
    #pragma unroll
    for (int i = 0; i < 3; i++) {
        int d = t + i * 256;
        float as = 0.f, ap = 0.f, an = 0.f;
        for (int r = s0; r < s1; r++) as += base[r * DD + d];
        for (int r = p0; r < p1; r++) ap += base[r * DD + d];
        for (int r = n0; r < n1; r++) an += base[r * DD + d];
        as *= inv_s; ap *= inv_p; an *= inv_n;
        g_sE[p * DD + d] = as;
        g_x[p * DD + d] = ap;
        g_x[(p + PP) * DD + d] = an;
        g_mem[p * 2 * DD + d] = base[d];
        g_mem[p * 2 * DD + DD + d] = as;
    }
}

// ---------------- TF32 GEMM body: BM=64, BN=64, BK=32, double-buffered ----------------
template <bool RELU, bool BIAS>
__device__ __forceinline__ void gemm_body(
    const float* __restrict__ A, const float* __restrict__ W,
    const float* __restrict__ bias, float* __restrict__ C,
    int K, int N, int kbeg, int kspan) {
    constexpr int BM = 64, BK = 32, BN = 64;
    constexpr int SAS = BK + 4;
    constexpr int SBS = BN + 4;
    __shared__ float sA[2][BM * SAS];
    __shared__ float sB[2][BK * SBS];

    int tid = threadIdx.x;
    int lane = tid & 31;
    int wid = tid >> 5;
    int wm = wid >> 2;
    int wn = wid & 3;
    int q = lane >> 2;
    int r4 = lane & 3;
    int row0 = blockIdx.y * BM;
    int col0 = blockIdx.x * BN;

    float acc[2][2][4];
    #pragma unroll
    for (int i = 0; i < 2; i++)
        #pragma unroll
        for (int j = 0; j < 2; j++)
            #pragma unroll
            for (int k = 0; k < 4; k++) acc[i][j][k] = 0.f;

    int arow0 = tid >> 3;
    int acol = (tid & 7) * 4;
    const float* Ag = A + (size_t)row0 * K;
    const float* Bg = W + col0;

    float4 pa[2], pb[2];

    auto loadg = [&](int k0) {
        pa[0] = *(const float4*)(Ag + (size_t)arow0 * K + k0 + acol);
        pa[1] = *(const float4*)(Ag + (size_t)(arow0 + 32) * K + k0 + acol);
        #pragma unroll
        for (int i = 0; i < 2; i++) {
            int idx = tid + i * 256;
            int br = idx >> 4;
            int bc = (idx & 15) * 4;
            pb[i] = *(const float4*)(Bg + (size_t)(k0 + br) * N + bc);
        }
    };
    auto stores = [&](int buf) {
        #pragma unroll
        for (int i = 0; i < 2; i++) {
            float4 v = pa[i];
            *(float4*)&sA[buf][(arow0 + i * 32) * SAS + acol] =
                make_float4(tf32r(v.x), tf32r(v.y), tf32r(v.z), tf32r(v.w));
        }
        #pragma unroll
        for (int i = 0; i < 2; i++) {
            int idx = tid + i * 256;
            int br = idx >> 4;
            int bc = (idx & 15) * 4;
            float4 v = pb[i];
            *(float4*)&sB[buf][br * SBS + bc] =
                make_float4(tf32r(v.x), tf32r(v.y), tf32r(v.z), tf32r(v.w));
        }
    };
    auto compute = [&](int buf) {
        #pragma unroll
        for (int ks = 0; ks < 4; ks++) {
            int kk = ks * 8;
            unsigned a[2][4];
            #pragma unroll
            for (int mt = 0; mt < 2; mt++) {
                int rr = wm * 32 + mt * 16 + q;
                a[mt][0] = __float_as_uint(sA[buf][rr * SAS + kk + r4]);
                a[mt][1] = __float_as_uint(sA[buf][(rr + 8) * SAS + kk + r4]);
                a[mt][2] = __float_as_uint(sA[buf][rr * SAS + kk + r4 + 4]);
                a[mt][3] = __float_as_uint(sA[buf][(rr + 8) * SAS + kk + r4 + 4]);
            }
            #pragma unroll
            for (int nt = 0; nt < 2; nt++) {
                int cc = wn * 16 + nt * 8 + q;
                unsigned b0 = __float_as_uint(sB[buf][(kk + r4) * SBS + cc]);
                unsigned b1 = __float_as_uint(sB[buf][(kk + 4 + r4) * SBS + cc]);
                mma_tf32(acc[0][nt], a[0], b0, b1);
                mma_tf32(acc[1][nt], a[1], b0, b1);
            }
        }
    };

    int niter = kspan / BK;
    loadg(kbeg);
    stores(0);
    __syncthreads();
    for (int it = 0; it < niter; it++) {
        int cur = it & 1;
        if (it + 1 < niter) loadg(kbeg + (it + 1) * BK);
        compute(cur);
        if (it + 1 < niter) stores(cur ^ 1);
        __syncthreads();
    }

    #pragma unroll
    for (int mt = 0; mt < 2; mt++) {
        int rr = row0 + wm * 32 + mt * 16 + q;
        #pragma unroll
        for (int nt = 0; nt < 2; nt++) {
            int cc = col0 + wn * 16 + nt * 8 + 2 * r4;
            float b0 = 0.f, b1 = 0.f;
            if (BIAS) { b0 = bias[cc]; b1 = bias[cc + 1]; }
            float v0 = acc[mt][nt][0] + b0;
            float v1 = acc[mt][nt][1] + b1;
            float v2 = acc[mt][nt][2] + b0;
            float v3 = acc[mt][nt][3] + b1;
            if (RELU) {
                v0 = fmaxf(v0, 0.f); v1 = fmaxf(v1, 0.f);
                v2 = fmaxf(v2, 0.f); v3 = fmaxf(v3, 0.f);
            }
            *(float2*)&C[(size_t)rr * N + cc] = make_float2(v0, v1);
            *(float2*)&C[(size_t)(rr + 8) * N + cc] = make_float2(v2, v3);
        }
    }
}

// ---------------- batched QKV GEMM (grid.z = 3) ----------------
__global__ __launch_bounds__(256) void tgemm_qkv(
    const float* __restrict__ mem, const float* __restrict__ xb,
    const float* __restrict__ Wk, const float* __restrict__ Wv, const float* __restrict__ Wq,
    const float* __restrict__ bk, const float* __restrict__ bv, const float* __restrict__ bq,
    float* __restrict__ Kb, float* __restrict__ Vb, float* __restrict__ qb) {
    int z = blockIdx.z;
    const float* A = (z == 2) ? xb : mem;
    const float* W = (z == 0) ? Wk : ((z == 1) ? Wv : Wq);
    const float* bias = (z == 0) ? bk : ((z == 1) ? bv : bq);
    float* C = (z == 0) ? Kb : ((z == 1) ? Vb : qb);
    gemm_body<false, true>(A, W, bias, C, DD, DD, 0, DD);
}

// ---------------- split-K GEMM ----------------
template <int SPLITK, bool RELU, bool BIAS>
__global__ __launch_bounds__(256) void tgemm_split(
    const float* __restrict__ A, const float* __restrict__ W,
    const float* __restrict__ bias, float* __restrict__ C,
    int M, int K, int N) {
    int z = blockIdx.z;
    int kspan = K / SPLITK;
    float* Cz = C + (size_t)z * M * N;
    gemm_body<RELU, BIAS>(A, W, bias, Cz, K, N, z * kspan, kspan);
}

// ---------------- 2-slot attention ----------------
__global__ void attn_kernel(const float* __restrict__ q, const float* __restrict__ Kb,
                            const float* __restrict__ Vb, float* __restrict__ o) {
    int rh = blockIdx.x;
    int r = rh / HH;
    int h = rh % HH;
    int p = r & (PP - 1);
    int d = threadIdx.x;
    size_t qoff = (size_t)r * DD + h * DH + d;
    size_t k0off = (size_t)p * 2 * DD + h * DH + d;
    float qd = q[qoff];
    float s0 = qd * Kb[k0off];
    float s1 = qd * Kb[k0off + DD];
    __shared__ float sh[4];
    #pragma unroll
    for (int off = 16; off > 0; off >>= 1) {
        s0 += __shfl_down_sync(0xffffffffu, s0, off);
        s1 += __shfl_down_sync(0xffffffffu, s1, off);
    }
    int w = threadIdx.x >> 5;
    if ((threadIdx.x & 31) == 0) { sh[w * 2] = s0; sh[w * 2 + 1] = s1; }
    __syncthreads();
    s0 = (sh[0] + sh[2]) * 0.125f;
    s1 = (sh[1] + sh[3]) * 0.125f;
    float m = fmaxf(s0, s1);
    float e0 = expf(s0 - m), e1 = expf(s1 - m);
    float inv = 1.f / (e0 + e1);
    o[qoff] = (e0 * inv) * Vb[k0off] + (e1 * inv) * Vb[k0off + DD];
}

// ---------------- residual + split-K combine + bias + LayerNorm ----------------
template <int NPARTS>
__global__ void add_ln_kernel(const float* __restrict__ x, const float* __restrict__ parts,
                              const float* __restrict__ bias,
                              const float* __restrict__ g, const float* __restrict__ b,
                              float* __restrict__ out) {
    int p = blockIdx.x;
    int t = threadIdx.x;
    __shared__ float sh[8];
    float v[3];
    float s = 0.f, s2 = 0.f;
    #pragma unroll
    for (int i = 0; i < 3; i++) {
        int d = t + i * 256;
        float acc = x[(size_t)p * DD + d] + bias[d];
        #pragma unroll
        for (int k = 0; k < NPARTS; k++)
            acc += parts[(size_t)k * M2 * DD + (size_t)p * DD + d];
        v[i] = acc;
        s += acc;
        s2 += acc * acc;
    }
    float sum = block_reduce_sum(s, sh);
    float sumsq = block_reduce_sum(s2, sh);
    float mean = sum * (1.0f / DD);
    float var = sumsq * (1.0f / DD) - mean * mean;
    float rstd = rsqrtf(var + EPS_LN);
    #pragma unroll
    for (int i = 0; i < 3; i++) {
        int d = t + i * 256;
        out[(size_t)p * DD + d] = (v[i] - mean) * rstd * g[d] + b[d];
    }
}

// ---------------- triplet loss ----------------
__global__ void loss_kernel(const float* __restrict__ sE, const float* __restrict__ att,
                            float* __restrict__ pl) {
    int p = blockIdx.x;
    int t = threadIdx.x;
    __shared__ float sh[8];
    float sp = 0.f, sn = 0.f;
    #pragma unroll
    for (int i = 0; i < 3; i++) {
        int d = t + i * 256;
        float a = sE[(size_t)p * DD + d] - att[(size_t)p * DD + d] + EPS_TRIP;
        float b = sE[(size_t)p * DD + d] - att[(size_t)(p + PP) * DD + d] + EPS_TRIP;
        sp += a * a;
        sn += b * b;
    }
    float SP = block_reduce_sum(sp, sh);
    float SN = block_reduce_sum(sn, sh);
    if (t == 0) pl[p] = fmaxf(sqrtf(SP) - sqrtf(SN) + 1.0f, 0.f);
}

__global__ void reduce_kernel(const float* __restrict__ pl, float* __restrict__ out) {
    int t = threadIdx.x;
    __shared__ float sh[8];
    float s = block_reduce_sum(pl[t], sh);
    if (t == 0) out[0] = s * (1.0f / PP);
}

// ---------------- host launch ----------------
extern "C" void kernel_launch(void* const* d_in, const int* in_sizes, int n_in,
                              void* d_out, int out_size) {
    const float* sent = (const float*)d_in[0];
    const int* sidx = (const int*)d_in[1];
    const int* ss = (const int*)d_in[2];
    const int* ps = (const int*)d_in[3];
    const int* ns = (const int*)d_in[4];
    const float* Wq = (const float*)d_in[5];
    const float* bq = (const float*)d_in[6];
    const float* Wk = (const float*)d_in[7];
    const float* bk = (const float*)d_in[8];
    const float* Wv = (const float*)d_in[9];
    const float* bv = (const float*)d_in[10];
    const float* Wo = (const float*)d_in[11];
    const float* bo = (const float*)d_in[12];
    const float* l1g = (const float*)d_in[13];
    const float* l1b = (const float*)d_in[14];
    const float* l2g = (const float*)d_in[15];
    const float* l2b = (const float*)d_in[16];
    const float* W1 = (const float*)d_in[17];
    const float* b1 = (const float*)d_in[18];
    const float* W2 = (const float*)d_in[19];
    const float* b2 = (const float*)d_in[20];
    float* out = (float*)d_out;

    float *mem, *sE, *xb, *Kb, *Vb, *qb, *ob, *ao, *hb, *f1, *f2, *att, *pl;
    cudaGetSymbolAddress((void**)&mem, g_mem);
    cudaGetSymbolAddress((void**)&sE, g_sE);
    cudaGetSymbolAddress((void**)&xb, g_x);
    cudaGetSymbolAddress((void**)&Kb, g_K);
    cudaGetSymbolAddress((void**)&Vb, g_V);
    cudaGetSymbolAddress((void**)&qb, g_q);
    cudaGetSymbolAddress((void**)&ob, g_o);
    cudaGetSymbolAddress((void**)&ao, g_ao);
    cudaGetSymbolAddress((void**)&hb, g_h);
    cudaGetSymbolAddress((void**)&f1, g_f1);
    cudaGetSymbolAddress((void**)&f2, g_f2);
    cudaGetSymbolAddress((void**)&att, g_att);
    cudaGetSymbolAddress((void**)&pl, g_pl);

    pool_kernel<<<PP, 256>>>(sent, sidx, ss, ps, ns);

    dim3 gQKV(DD / 64, M2 / 64, 3);    // 12 x 8 x 3 = 288 blocks
    dim3 gWo(DD / 64, M2 / 64, 2);     // split-K 2 -> 192 blocks
    dim3 gW1(DFF / 64, M2 / 64, 1);    // 48 x 8 = 384 blocks
    dim3 gW2(DD / 64, M2 / 64, 4);     // split-K 4 -> 384 blocks

    tgemm_qkv<<<gQKV, 256>>>(mem, xb, Wk, Wv, Wq, bk, bv, bq, Kb, Vb, qb);
    attn_kernel<<<M2 * HH, 64>>>(qb, Kb, Vb, ob);
    tgemm_split<2, false, false><<<gWo, 256>>>(ob, Wo, nullptr, ao, M2, DD, DD);
    add_ln_kernel<2><<<M2, 256>>>(xb, ao, bo, l1g, l1b, hb);
    tgemm_split<1, true, true><<<gW1, 256>>>(hb, W1, b1, f1, M2, DD, DFF);
    tgemm_split<4, false, false><<<gW2, 256>>>(f1, W2, nullptr, f2, M2, DFF, DD);
    add_ln_kernel<4><<<M2, 256>>>(hb, f2, b2, l2g, l2b, att);

    loss_kernel<<<PP, 256>>>(sE, att, pl);
    reduce_kernel<<<1, 256>>>(pl, out);
}

// round 4
// speedup vs baseline: 5.9665x; 1.0225x over previous
#include <cuda_runtime.h>
#include <math.h>

#define SS 512
#define DD 768
#define PP 256
#define HH 12
#define DH 64
#define DFF 3072
#define M2 (2*PP)
#define EPS_LN 1e-5f
#define EPS_TRIP 1e-6f

// ---------------- scratch ----------------
__device__ float g_mem[M2 * DD];
__device__ float g_sE[PP * DD];
__device__ float g_x[M2 * DD];
__device__ float g_K[M2 * DD];
__device__ float g_V[M2 * DD];
__device__ float g_q[M2 * DD];
__device__ float g_o[M2 * DD];
__device__ float g_ao[4 * M2 * DD];   // 4 split-K partials
__device__ float g_h[M2 * DD];
__device__ float g_f1[M2 * DFF];
__device__ float g_f2[8 * M2 * DD];   // 8 split-K partials
__device__ float g_att[M2 * DD];
__device__ float g_pl[PP];

// ---------------- helpers ----------------
__device__ __forceinline__ void mma_tf32(float* c, const unsigned* a, unsigned b0, unsigned b1) {
    asm volatile(
        "mma.sync.aligned.m16n8k8.row.col.f32.tf32.tf32.f32 "
        "{%0,%1,%2,%3}, {%4,%5,%6,%7}, {%8,%9}, {%0,%1,%2,%3};"
        : "+f"(c[0]), "+f"(c[1]), "+f"(c[2]), "+f"(c[3])
        : "r"(a[0]), "r"(a[1]), "r"(a[2]), "r"(a[3]), "r"(b0), "r"(b1));
}

__device__ __forceinline__ void cp16(unsigned saddr, const void* gaddr) {
    asm volatile("cp.async.ca.shared.global [%0], [%1], 16;\n" :: "r"(saddr), "l"(gaddr));
}
__device__ __forceinline__ void cp_commit() {
    asm volatile("cp.async.commit_group;\n" ::);
}
__device__ __forceinline__ void cp_wait0() {
    asm volatile("cp.async.wait_group 0;\n" ::);
}

__device__ __forceinline__ float block_reduce_sum(float v, float* sh) {
    int lane = threadIdx.x & 31;
    int w = threadIdx.x >> 5;
    #pragma unroll
    for (int o = 16; o > 0; o >>= 1) v += __shfl_down_sync(0xffffffffu, v, o);
    __syncthreads();
    if (lane == 0) sh[w] = v;
    __syncthreads();
    int nw = blockDim.x >> 5;
    float r = (threadIdx.x < nw) ? sh[threadIdx.x] : 0.f;
    if (w == 0) {
        #pragma unroll
        for (int o = 16; o > 0; o >>= 1) r += __shfl_down_sync(0xffffffffu, r, o);
        if (lane == 0) sh[0] = r;
    }
    __syncthreads();
    return sh[0];
}

// ---------------- pooling ----------------
__global__ void pool_kernel(const float* __restrict__ se, const int* __restrict__ sidx,
                            const int* __restrict__ ss, const int* __restrict__ ps,
                            const int* __restrict__ ns) {
    int p = blockIdx.x;
    const float* base = se + (size_t)sidx[p] * SS * DD;
    int t = threadIdx.x;
    int s0 = ss[2 * p], s1 = ss[2 * p + 1];
    int p0 = ps[2 * p], p1 = ps[2 * p + 1];
    int n0 = ns[2 * p], n1 = ns[2 * p + 1];
    float inv_s = 1.0f / (float)(s1 - s0);
    float inv_p = 1.0f / (float)(p1 - p0);
    float inv_n = 1.0f / (float)(n1 - n0);
    #pragma unroll
    for (int i = 0; i < 3; i++) {
        int d = t + i * 256;
        float as = 0.f, ap = 0.f, an = 0.f;
        for (int r = s0; r < s1; r++) as += base[r * DD + d];
        for (int r = p0; r < p1; r++) ap += base[r * DD + d];
        for (int r = n0; r < n1; r++) an += base[r * DD + d];
        as *= inv_s; ap *= inv_p; an *= inv_n;
        g_sE[p * DD + d] = as;
        g_x[p * DD + d] = ap;
        g_x[(p + PP) * DD + d] = an;
        g_mem[p * 2 * DD + d] = base[d];
        g_mem[p * 2 * DD + DD + d] = as;
    }
}

// ---------------- TF32 GEMM body: BM=64, BN=64, BK=32, cp.async double-buffered ----------------
template <bool RELU, bool BIAS>
__device__ __forceinline__ void gemm_body(
    const float* __restrict__ A, const float* __restrict__ W,
    const float* __restrict__ bias, float* __restrict__ C,
    int K, int N, int kbeg, int kspan) {
    constexpr int BM = 64, BK = 32, BN = 64;
    constexpr int SAS = BK + 4;
    constexpr int SBS = BN + 4;
    __shared__ float sA[2][BM * SAS];
    __shared__ float sB[2][BK * SBS];

    int tid = threadIdx.x;
    int lane = tid & 31;
    int wid = tid >> 5;
    int wm = wid >> 2;
    int wn = wid & 3;
    int q = lane >> 2;
    int r4 = lane & 3;
    int row0 = blockIdx.y * BM;
    int col0 = blockIdx.x * BN;

    float acc[2][2][4];
    #pragma unroll
    for (int i = 0; i < 2; i++)
        #pragma unroll
        for (int j = 0; j < 2; j++)
            #pragma unroll
            for (int k = 0; k < 4; k++) acc[i][j][k] = 0.f;

    int arow = tid >> 3;
    int acol = (tid & 7) * 4;
    int brow = tid >> 4;                 // 0..15 (first half); +16 for second
    int bcol = (tid & 15) * 4;
    const float* Ag = A + (size_t)(row0 + arow) * K + acol;
    const float* Bg = W + col0 + bcol;

    unsigned sAu[2], sBu[2];
    sAu[0] = (unsigned)__cvta_generic_to_shared(&sA[0][0]);
    sAu[1] = (unsigned)__cvta_generic_to_shared(&sA[1][0]);
    sBu[0] = (unsigned)__cvta_generic_to_shared(&sB[0][0]);
    sBu[1] = (unsigned)__cvta_generic_to_shared(&sB[1][0]);

    auto issue = [&](int k0, int buf) {
        cp16(sAu[buf] + (arow * SAS + acol) * 4, Ag + k0);
        cp16(sAu[buf] + ((arow + 32) * SAS + acol) * 4, Ag + (size_t)32 * K + k0);
        cp16(sBu[buf] + (brow * SBS + bcol) * 4, Bg + (size_t)(k0 + brow) * N);
        cp16(sBu[buf] + ((brow + 16) * SBS + bcol) * 4, Bg + (size_t)(k0 + brow + 16) * N);
        cp_commit();
    };

    auto compute = [&](int buf) {
        #pragma unroll
        for (int ks = 0; ks < 4; ks++) {
            int kk = ks * 8;
            unsigned a[2][4];
            #pragma unroll
            for (int mt = 0; mt < 2; mt++) {
                int rr = wm * 32 + mt * 16 + q;
                a[mt][0] = __float_as_uint(sA[buf][rr * SAS + kk + r4]);
                a[mt][1] = __float_as_uint(sA[buf][(rr + 8) * SAS + kk + r4]);
                a[mt][2] = __float_as_uint(sA[buf][rr * SAS + kk + r4 + 4]);
                a[mt][3] = __float_as_uint(sA[buf][(rr + 8) * SAS + kk + r4 + 4]);
            }
            #pragma unroll
            for (int nt = 0; nt < 2; nt++) {
                int cc = wn * 16 + nt * 8 + q;
                unsigned b0 = __float_as_uint(sB[buf][(kk + r4) * SBS + cc]);
                unsigned b1 = __float_as_uint(sB[buf][(kk + 4 + r4) * SBS + cc]);
                mma_tf32(acc[0][nt], a[0], b0, b1);
                mma_tf32(acc[1][nt], a[1], b0, b1);
            }
        }
    };

    int niter = kspan / BK;
    issue(kbeg, 0);
    for (int it = 0; it < niter; it++) {
        int cur = it & 1;
        cp_wait0();
        __syncthreads();
        if (it + 1 < niter) issue(kbeg + (it + 1) * BK, cur ^ 1);
        compute(cur);
    }

    #pragma unroll
    for (int mt = 0; mt < 2; mt++) {
        int rr = row0 + wm * 32 + mt * 16 + q;
        #pragma unroll
        for (int nt = 0; nt < 2; nt++) {
            int cc = col0 + wn * 16 + nt * 8 + 2 * r4;
            float b0 = 0.f, b1 = 0.f;
            if (BIAS) { b0 = bias[cc]; b1 = bias[cc + 1]; }
            float v0 = acc[mt][nt][0] + b0;
            float v1 = acc[mt][nt][1] + b1;
            float v2 = acc[mt][nt][2] + b0;
            float v3 = acc[mt][nt][3] + b1;
            if (RELU) {
                v0 = fmaxf(v0, 0.f); v1 = fmaxf(v1, 0.f);
                v2 = fmaxf(v2, 0.f); v3 = fmaxf(v3, 0.f);
            }
            *(float2*)&C[(size_t)rr * N + cc] = make_float2(v0, v1);
            *(float2*)&C[(size_t)(rr + 8) * N + cc] = make_float2(v2, v3);
        }
    }
}

// ---------------- batched QKV GEMM (grid.z = 3) ----------------
__global__ __launch_bounds__(256) void tgemm_qkv(
    const float* __restrict__ mem, const float* __restrict__ xb,
    const float* __restrict__ Wk, const float* __restrict__ Wv, const float* __restrict__ Wq,
    const float* __restrict__ bk, const float* __restrict__ bv, const float* __restrict__ bq,
    float* __restrict__ Kb, float* __restrict__ Vb, float* __restrict__ qb) {
    int z = blockIdx.z;
    const float* A = (z == 2) ? xb : mem;
    const float* W = (z == 0) ? Wk : ((z == 1) ? Wv : Wq);
    const float* bias = (z == 0) ? bk : ((z == 1) ? bv : bq);
    float* C = (z == 0) ? Kb : ((z == 1) ? Vb : qb);
    gemm_body<false, true>(A, W, bias, C, DD, DD, 0, DD);
}

// ---------------- split-K GEMM ----------------
template <int SPLITK, bool RELU, bool BIAS>
__global__ __launch_bounds__(256) void tgemm_split(
    const float* __restrict__ A, const float* __restrict__ W,
    const float* __restrict__ bias, float* __restrict__ C,
    int M, int K, int N) {
    int z = blockIdx.z;
    int kspan = K / SPLITK;
    float* Cz = C + (size_t)z * M * N;
    gemm_body<RELU, BIAS>(A, W, bias, Cz, K, N, z * kspan, kspan);
}

// ---------------- 2-slot attention ----------------
__global__ void attn_kernel(const float* __restrict__ q, const float* __restrict__ Kb,
                            const float* __restrict__ Vb, float* __restrict__ o) {
    int rh = blockIdx.x;
    int r = rh / HH;
    int h = rh % HH;
    int p = r & (PP - 1);
    int d = threadIdx.x;
    size_t qoff = (size_t)r * DD + h * DH + d;
    size_t k0off = (size_t)p * 2 * DD + h * DH + d;
    float qd = q[qoff];
    float s0 = qd * Kb[k0off];
    float s1 = qd * Kb[k0off + DD];
    __shared__ float sh[4];
    #pragma unroll
    for (int off = 16; off > 0; off >>= 1) {
        s0 += __shfl_down_sync(0xffffffffu, s0, off);
        s1 += __shfl_down_sync(0xffffffffu, s1, off);
    }
    int w = threadIdx.x >> 5;
    if ((threadIdx.x & 31) == 0) { sh[w * 2] = s0; sh[w * 2 + 1] = s1; }
    __syncthreads();
    s0 = (sh[0] + sh[2]) * 0.125f;
    s1 = (sh[1] + sh[3]) * 0.125f;
    float m = fmaxf(s0, s1);
    float e0 = expf(s0 - m), e1 = expf(s1 - m);
    float inv = 1.f / (e0 + e1);
    o[qoff] = (e0 * inv) * Vb[k0off] + (e1 * inv) * Vb[k0off + DD];
}

// ---------------- residual + split-K combine + bias + LayerNorm ----------------
template <int NPARTS>
__global__ void add_ln_kernel(const float* __restrict__ x, const float* __restrict__ parts,
                              const float* __restrict__ bias,
                              const float* __restrict__ g, const float* __restrict__ b,
                              float* __restrict__ out) {
    int p = blockIdx.x;
    int t = threadIdx.x;
    __shared__ float sh[8];
    float v[3];
    float s = 0.f, s2 = 0.f;
    #pragma unroll
    for (int i = 0; i < 3; i++) {
        int d = t + i * 256;
        float acc = x[(size_t)p * DD + d] + bias[d];
        #pragma unroll
        for (int k = 0; k < NPARTS; k++)
            acc += parts[(size_t)k * M2 * DD + (size_t)p * DD + d];
        v[i] = acc;
        s += acc;
        s2 += acc * acc;
    }
    float sum = block_reduce_sum(s, sh);
    float sumsq = block_reduce_sum(s2, sh);
    float mean = sum * (1.0f / DD);
    float var = sumsq * (1.0f / DD) - mean * mean;
    float rstd = rsqrtf(var + EPS_LN);
    #pragma unroll
    for (int i = 0; i < 3; i++) {
        int d = t + i * 256;
        out[(size_t)p * DD + d] = (v[i] - mean) * rstd * g[d] + b[d];
    }
}

// ---------------- triplet loss ----------------
__global__ void loss_kernel(const float* __restrict__ sE, const float* __restrict__ att,
                            float* __restrict__ pl) {
    int p = blockIdx.x;
    int t = threadIdx.x;
    __shared__ float sh[8];
    float sp = 0.f, sn = 0.f;
    #pragma unroll
    for (int i = 0; i < 3; i++) {
        int d = t + i * 256;
        float a = sE[(size_t)p * DD + d] - att[(size_t)p * DD + d] + EPS_TRIP;
        float b = sE[(size_t)p * DD + d] - att[(size_t)(p + PP) * DD + d] + EPS_TRIP;
        sp += a * a;
        sn += b * b;
    }
    float SP = block_reduce_sum(sp, sh);
    float SN = block_reduce_sum(sn, sh);
    if (t == 0) pl[p] = fmaxf(sqrtf(SP) - sqrtf(SN) + 1.0f, 0.f);
}

__global__ void reduce_kernel(const float* __restrict__ pl, float* __restrict__ out) {
    int t = threadIdx.x;
    __shared__ float sh[8];
    float s = block_reduce_sum(pl[t], sh);
    if (t == 0) out[0] = s * (1.0f / PP);
}

// ---------------- host launch ----------------
extern "C" void kernel_launch(void* const* d_in, const int* in_sizes, int n_in,
                              void* d_out, int out_size) {
    const float* sent = (const float*)d_in[0];
    const int* sidx = (const int*)d_in[1];
    const int* ss = (const int*)d_in[2];
    const int* ps = (const int*)d_in[3];
    const int* ns = (const int*)d_in[4];
    const float* Wq = (const float*)d_in[5];
    const float* bq = (const float*)d_in[6];
    const float* Wk = (const float*)d_in[7];
    const float* bk = (const float*)d_in[8];
    const float* Wv = (const float*)d_in[9];
    const float* bv = (const float*)d_in[10];
    const float* Wo = (const float*)d_in[11];
    const float* bo = (const float*)d_in[12];
    const float* l1g = (const float*)d_in[13];
    const float* l1b = (const float*)d_in[14];
    const float* l2g = (const float*)d_in[15];
    const float* l2b = (const float*)d_in[16];
    const float* W1 = (const float*)d_in[17];
    const float* b1 = (const float*)d_in[18];
    const float* W2 = (const float*)d_in[19];
    const float* b2 = (const float*)d_in[20];
    float* out = (float*)d_out;

    float *mem, *sE, *xb, *Kb, *Vb, *qb, *ob, *ao, *hb, *f1, *f2, *att, *pl;
    cudaGetSymbolAddress((void**)&mem, g_mem);
    cudaGetSymbolAddress((void**)&sE, g_sE);
    cudaGetSymbolAddress((void**)&xb, g_x);
    cudaGetSymbolAddress((void**)&Kb, g_K);
    cudaGetSymbolAddress((void**)&Vb, g_V);
    cudaGetSymbolAddress((void**)&qb, g_q);
    cudaGetSymbolAddress((void**)&ob, g_o);
    cudaGetSymbolAddress((void**)&ao, g_ao);
    cudaGetSymbolAddress((void**)&hb, g_h);
    cudaGetSymbolAddress((void**)&f1, g_f1);
    cudaGetSymbolAddress((void**)&f2, g_f2);
    cudaGetSymbolAddress((void**)&att, g_att);
    cudaGetSymbolAddress((void**)&pl, g_pl);

    pool_kernel<<<PP, 256>>>(sent, sidx, ss, ps, ns);

    dim3 gQKV(DD / 64, M2 / 64, 3);    // 288 blocks
    dim3 gWo(DD / 64, M2 / 64, 4);     // split-K 4 -> 384 blocks, 6 iters each
    dim3 gW1(DFF / 64, M2 / 64, 1);    // 384 blocks
    dim3 gW2(DD / 64, M2 / 64, 8);     // split-K 8 -> 768 blocks, 12 iters each

    tgemm_qkv<<<gQKV, 256>>>(mem, xb, Wk, Wv, Wq, bk, bv, bq, Kb, Vb, qb);
    attn_kernel<<<M2 * HH, 64>>>(qb, Kb, Vb, ob);
    tgemm_split<4, false, false><<<gWo, 256>>>(ob, Wo, nullptr, ao, M2, DD, DD);
    add_ln_kernel<4><<<M2, 256>>>(xb, ao, bo, l1g, l1b, hb);
    tgemm_split<1, true, true><<<gW1, 256>>>(hb, W1, b1, f1, M2, DD, DFF);
    tgemm_split<8, false, false><<<gW2, 256>>>(f1, W2, nullptr, f2, M2, DFF, DD);
    add_ln_kernel<8><<<M2, 256>>>(hb, f2, b2, l2g, l2b, att);

    loss_kernel<<<PP, 256>>>(sE, att, pl);
    reduce_kernel<<<1, 256>>>(pl, out);
}

// round 5
// speedup vs baseline: 7.3583x; 1.2333x over previous
#include <cuda_runtime.h>
#include <math.h>

#define SS 512
#define DD 768
#define PP 256
#define HH 12
#define DH 64
#define DFF 3072
#define M2 (2*PP)
#define EPS_LN 1e-5f
#define EPS_TRIP 1e-6f

// GEMM tile config: BM=64, BN=64, BK=32, 128 threads (4 warps, 2x2), warp tile 32x32
#define SAS 36
#define SBS 72
#define ASZ (64 * SAS)
#define BSZ (32 * SBS)
#define NSTAGE 3
#define SMEM_BYTES (NSTAGE * (ASZ + BSZ) * 4)

// ---------------- scratch ----------------
__device__ float g_mem[M2 * DD];
__device__ float g_sE[PP * DD];
__device__ float g_x[M2 * DD];
__device__ float g_K[M2 * DD];
__device__ float g_V[M2 * DD];
__device__ float g_q[M2 * DD];
__device__ float g_o[M2 * DD];
__device__ float g_ao[4 * M2 * DD];
__device__ float g_h[M2 * DD];
__device__ float g_f1[M2 * DFF];
__device__ float g_f2[8 * M2 * DD];
__device__ float g_pl[PP];

// ---------------- helpers ----------------
__device__ __forceinline__ void mma_tf32(float* c, const unsigned* a, unsigned b0, unsigned b1) {
    asm volatile(
        "mma.sync.aligned.m16n8k8.row.col.f32.tf32.tf32.f32 "
        "{%0,%1,%2,%3}, {%4,%5,%6,%7}, {%8,%9}, {%0,%1,%2,%3};"
        : "+f"(c[0]), "+f"(c[1]), "+f"(c[2]), "+f"(c[3])
        : "r"(a[0]), "r"(a[1]), "r"(a[2]), "r"(a[3]), "r"(b0), "r"(b1));
}

__device__ __forceinline__ void cp16(unsigned saddr, const void* gaddr) {
    asm volatile("cp.async.ca.shared.global [%0], [%1], 16;\n" :: "r"(saddr), "l"(gaddr));
}
__device__ __forceinline__ void cp_commit() {
    asm volatile("cp.async.commit_group;\n" ::);
}
__device__ __forceinline__ void cp_wait1() {
    asm volatile("cp.async.wait_group 1;\n" ::);
}

__device__ __forceinline__ float block_reduce_sum(float v, float* sh) {
    int lane = threadIdx.x & 31;
    int w = threadIdx.x >> 5;
    #pragma unroll
    for (int o = 16; o > 0; o >>= 1) v += __shfl_down_sync(0xffffffffu, v, o);
    __syncthreads();
    if (lane == 0) sh[w] = v;
    __syncthreads();
    int nw = blockDim.x >> 5;
    float r = (threadIdx.x < nw) ? sh[threadIdx.x] : 0.f;
    if (w == 0) {
        #pragma unroll
        for (int o = 16; o > 0; o >>= 1) r += __shfl_down_sync(0xffffffffu, r, o);
        if (lane == 0) sh[0] = r;
    }
    __syncthreads();
    return sh[0];
}

// ---------------- pooling ----------------
__global__ void pool_kernel(const float* __restrict__ se, const int* __restrict__ sidx,
                            const int* __restrict__ ss, const int* __restrict__ ps,
                            const int* __restrict__ ns) {
    int p = blockIdx.x;
    const float* base = se + (size_t)sidx[p] * SS * DD;
    int t = threadIdx.x;
    int s0 = ss[2 * p], s1 = ss[2 * p + 1];
    int p0 = ps[2 * p], p1 = ps[2 * p + 1];
    int n0 = ns[2 * p], n1 = ns[2 * p + 1];
    float inv_s = 1.0f / (float)(s1 - s0);
    float inv_p = 1.0f / (float)(p1 - p0);
    float inv_n = 1.0f / (float)(n1 - n0);
    #pragma unroll
    for (int i = 0; i < 3; i++) {
        int d = t + i * 256;
        float as = 0.f, ap = 0.f, an = 0.f;
        for (int r = s0; r < s1; r++) as += base[r * DD + d];
        for (int r = p0; r < p1; r++) ap += base[r * DD + d];
        for (int r = n0; r < n1; r++) an += base[r * DD + d];
        as *= inv_s; ap *= inv_p; an *= inv_n;
        g_sE[p * DD + d] = as;
        g_x[p * DD + d] = ap;
        g_x[(p + PP) * DD + d] = an;
        g_mem[p * 2 * DD + d] = base[d];
        g_mem[p * 2 * DD + DD + d] = as;
    }
}

// ---------------- TF32 GEMM body: 128 threads, warp tile 32x32, 3-stage cp.async ----------------
template <bool RELU, bool BIAS>
__device__ __forceinline__ void gemm_body(
    const float* __restrict__ A, const float* __restrict__ W,
    const float* __restrict__ bias, float* __restrict__ C,
    int K, int N, int kbeg, int kspan) {
    constexpr int BM = 64, BK = 32, BN = 64;
    extern __shared__ float smem[];
    float* sA = smem;                       // NSTAGE * ASZ
    float* sB = smem + NSTAGE * ASZ;        // NSTAGE * BSZ

    int tid = threadIdx.x;
    int lane = tid & 31;
    int wid = tid >> 5;
    int wm = wid >> 1;                      // 0..1
    int wn = wid & 1;                       // 0..1
    int q = lane >> 2;                      // 0..7
    int r4 = lane & 3;                      // 0..3
    int row0 = blockIdx.y * BM;
    int col0 = blockIdx.x * BN;

    float acc[2][4][4];
    #pragma unroll
    for (int i = 0; i < 2; i++)
        #pragma unroll
        for (int j = 0; j < 4; j++)
            #pragma unroll
            for (int k = 0; k < 4; k++) acc[i][j][k] = 0.f;

    unsigned uA = (unsigned)__cvta_generic_to_shared(sA);
    unsigned uB = (unsigned)__cvta_generic_to_shared(sB);

    int niter = kspan / BK;

    auto issue = [&](int it) {
        if (it < niter) {
            int k0 = kbeg + it * BK;
            int s = it % NSTAGE;
            unsigned dA = uA + s * ASZ * 4;
            unsigned dB = uB + s * BSZ * 4;
            #pragma unroll
            for (int i = 0; i < 4; i++) {
                int idx = tid + i * 128;
                int ar = idx >> 3;
                int ac = (idx & 7) * 4;
                cp16(dA + (ar * SAS + ac) * 4, A + (size_t)(row0 + ar) * K + k0 + ac);
                int br = idx >> 4;
                int bc = (idx & 15) * 4;
                cp16(dB + (br * SBS + bc) * 4, W + (size_t)(k0 + br) * N + col0 + bc);
            }
        }
        cp_commit();
    };

    auto compute = [&](int it) {
        int s = it % NSTAGE;
        const float* cA = sA + s * ASZ;
        const float* cB = sB + s * BSZ;
        #pragma unroll
        for (int ks = 0; ks < 4; ks++) {
            int kk = ks * 8;
            unsigned a[2][4];
            #pragma unroll
            for (int mt = 0; mt < 2; mt++) {
                int rr = wm * 32 + mt * 16 + q;
                a[mt][0] = __float_as_uint(cA[rr * SAS + kk + r4]);
                a[mt][1] = __float_as_uint(cA[(rr + 8) * SAS + kk + r4]);
                a[mt][2] = __float_as_uint(cA[rr * SAS + kk + r4 + 4]);
                a[mt][3] = __float_as_uint(cA[(rr + 8) * SAS + kk + r4 + 4]);
            }
            #pragma unroll
            for (int nt = 0; nt < 4; nt++) {
                int cc = wn * 32 + nt * 8 + q;
                unsigned b0 = __float_as_uint(cB[(kk + r4) * SBS + cc]);
                unsigned b1 = __float_as_uint(cB[(kk + 4 + r4) * SBS + cc]);
                mma_tf32(acc[0][nt], a[0], b0, b1);
                mma_tf32(acc[1][nt], a[1], b0, b1);
            }
        }
    };

    issue(0);
    issue(1);
    for (int it = 0; it < niter; it++) {
        cp_wait1();
        __syncthreads();
        issue(it + 2);
        compute(it);
    }

    #pragma unroll
    for (int mt = 0; mt < 2; mt++) {
        int rr = row0 + wm * 32 + mt * 16 + q;
        #pragma unroll
        for (int nt = 0; nt < 4; nt++) {
            int cc = col0 + wn * 32 + nt * 8 + 2 * r4;
            float b0 = 0.f, b1 = 0.f;
            if (BIAS) { b0 = bias[cc]; b1 = bias[cc + 1]; }
            float v0 = acc[mt][nt][0] + b0;
            float v1 = acc[mt][nt][1] + b1;
            float v2 = acc[mt][nt][2] + b0;
            float v3 = acc[mt][nt][3] + b1;
            if (RELU) {
                v0 = fmaxf(v0, 0.f); v1 = fmaxf(v1, 0.f);
                v2 = fmaxf(v2, 0.f); v3 = fmaxf(v3, 0.f);
            }
            *(float2*)&C[(size_t)rr * N + cc] = make_float2(v0, v1);
            *(float2*)&C[(size_t)(rr + 8) * N + cc] = make_float2(v2, v3);
        }
    }
}

// ---------------- batched QKV GEMM ----------------
__global__ __launch_bounds__(128) void tgemm_qkv(
    const float* __restrict__ mem, const float* __restrict__ xb,
    const float* __restrict__ Wk, const float* __restrict__ Wv, const float* __restrict__ Wq,
    const float* __restrict__ bk, const float* __restrict__ bv, const float* __restrict__ bq,
    float* __restrict__ Kb, float* __restrict__ Vb, float* __restrict__ qb) {
    int z = blockIdx.z;
    const float* A = (z == 2) ? xb : mem;
    const float* W = (z == 0) ? Wk : ((z == 1) ? Wv : Wq);
    const float* bias = (z == 0) ? bk : ((z == 1) ? bv : bq);
    float* C = (z == 0) ? Kb : ((z == 1) ? Vb : qb);
    gemm_body<false, true>(A, W, bias, C, DD, DD, 0, DD);
}

// ---------------- split-K GEMM ----------------
template <int SPLITK, bool RELU, bool BIAS>
__global__ __launch_bounds__(128) void tgemm_split(
    const float* __restrict__ A, const float* __restrict__ W,
    const float* __restrict__ bias, float* __restrict__ C,
    int M, int K, int N) {
    int z = blockIdx.z;
    int kspan = K / SPLITK;
    float* Cz = C + (size_t)z * M * N;
    gemm_body<RELU, BIAS>(A, W, bias, Cz, K, N, z * kspan, kspan);
}

// ---------------- 2-slot attention ----------------
__global__ void attn_kernel(const float* __restrict__ q, const float* __restrict__ Kb,
                            const float* __restrict__ Vb, float* __restrict__ o) {
    int rh = blockIdx.x;
    int r = rh / HH;
    int h = rh % HH;
    int p = r & (PP - 1);
    int d = threadIdx.x;
    size_t qoff = (size_t)r * DD + h * DH + d;
    size_t k0off = (size_t)p * 2 * DD + h * DH + d;
    float qd = q[qoff];
    float s0 = qd * Kb[k0off];
    float s1 = qd * Kb[k0off + DD];
    __shared__ float sh[4];
    #pragma unroll
    for (int off = 16; off > 0; off >>= 1) {
        s0 += __shfl_down_sync(0xffffffffu, s0, off);
        s1 += __shfl_down_sync(0xffffffffu, s1, off);
    }
    int w = threadIdx.x >> 5;
    if ((threadIdx.x & 31) == 0) { sh[w * 2] = s0; sh[w * 2 + 1] = s1; }
    __syncthreads();
    s0 = (sh[0] + sh[2]) * 0.125f;
    s1 = (sh[1] + sh[3]) * 0.125f;
    float m = fmaxf(s0, s1);
    float e0 = expf(s0 - m), e1 = expf(s1 - m);
    float inv = 1.f / (e0 + e1);
    o[qoff] = (e0 * inv) * Vb[k0off] + (e1 * inv) * Vb[k0off + DD];
}

// ---------------- residual + split-K combine + bias + LayerNorm ----------------
template <int NPARTS>
__global__ void add_ln_kernel(const float* __restrict__ x, const float* __restrict__ parts,
                              const float* __restrict__ bias,
                              const float* __restrict__ g, const float* __restrict__ b,
                              float* __restrict__ out) {
    int p = blockIdx.x;
    int t = threadIdx.x;
    __shared__ float sh[8];
    float v[3];
    float s = 0.f, s2 = 0.f;
    #pragma unroll
    for (int i = 0; i < 3; i++) {
        int d = t + i * 256;
        float acc = x[(size_t)p * DD + d] + bias[d];
        #pragma unroll
        for (int k = 0; k < NPARTS; k++)
            acc += parts[(size_t)k * M2 * DD + (size_t)p * DD + d];
        v[i] = acc;
        s += acc;
        s2 += acc * acc;
    }
    float sum = block_reduce_sum(s, sh);
    float sumsq = block_reduce_sum(s2, sh);
    float mean = sum * (1.0f / DD);
    float var = sumsq * (1.0f / DD) - mean * mean;
    float rstd = rsqrtf(var + EPS_LN);
    #pragma unroll
    for (int i = 0; i < 3; i++) {
        int d = t + i * 256;
        out[(size_t)p * DD + d] = (v[i] - mean) * rstd * g[d] + b[d];
    }
}

// ---------------- fused: 2nd add+LN (8 partials) for rows p and p+PP, + triplet loss ----------------
__global__ void add_ln_loss_kernel(const float* __restrict__ hb, const float* __restrict__ parts,
                                   const float* __restrict__ bias,
                                   const float* __restrict__ g, const float* __restrict__ b,
                                   const float* __restrict__ sE, float* __restrict__ pl) {
    int p = blockIdx.x;            // 0..PP-1
    int t = threadIdx.x;           // 256
    __shared__ float sh[8];
    float vp[3], vn[3];
    float sp = 0.f, sp2 = 0.f, sn = 0.f, sn2 = 0.f;
    #pragma unroll
    for (int i = 0; i < 3; i++) {
        int d = t + i * 256;
        float ap = hb[(size_t)p * DD + d] + bias[d];
        float an = hb[(size_t)(p + PP) * DD + d] + bias[d];
        #pragma unroll
        for (int k = 0; k < 8; k++) {
            ap += parts[(size_t)k * M2 * DD + (size_t)p * DD + d];
            an += parts[(size_t)k * M2 * DD + (size_t)(p + PP) * DD + d];
        }
        vp[i] = ap; vn[i] = an;
        sp += ap; sp2 += ap * ap;
        sn += an; sn2 += an * an;
    }
    float sump = block_reduce_sum(sp, sh);
    float sumsqp = block_reduce_sum(sp2, sh);
    float sumn = block_reduce_sum(sn, sh);
    float sumsqn = block_reduce_sum(sn2, sh);
    float meanp = sump * (1.0f / DD);
    float rstdp = rsqrtf(sumsqp * (1.0f / DD) - meanp * meanp + EPS_LN);
    float meann = sumn * (1.0f / DD);
    float rstdn = rsqrtf(sumsqn * (1.0f / DD) - meann * meann + EPS_LN);
    float dp = 0.f, dn = 0.f;
    #pragma unroll
    for (int i = 0; i < 3; i++) {
        int d = t + i * 256;
        float attp = (vp[i] - meanp) * rstdp * g[d] + b[d];
        float attn = (vn[i] - meann) * rstdn * g[d] + b[d];
        float e = sE[(size_t)p * DD + d];
        float a = e - attp + EPS_TRIP;
        float c = e - attn + EPS_TRIP;
        dp += a * a;
        dn += c * c;
    }
    float DP = block_reduce_sum(dp, sh);
    float DN = block_reduce_sum(dn, sh);
    if (t == 0) pl[p] = fmaxf(sqrtf(DP) - sqrtf(DN) + 1.0f, 0.f);
}

__global__ void reduce_kernel(const float* __restrict__ pl, float* __restrict__ out) {
    int t = threadIdx.x;
    __shared__ float sh[8];
    float s = block_reduce_sum(pl[t], sh);
    if (t == 0) out[0] = s * (1.0f / PP);
}

// ---------------- host launch ----------------
extern "C" void kernel_launch(void* const* d_in, const int* in_sizes, int n_in,
                              void* d_out, int out_size) {
    const float* sent = (const float*)d_in[0];
    const int* sidx = (const int*)d_in[1];
    const int* ss = (const int*)d_in[2];
    const int* ps = (const int*)d_in[3];
    const int* ns = (const int*)d_in[4];
    const float* Wq = (const float*)d_in[5];
    const float* bq = (const float*)d_in[6];
    const float* Wk = (const float*)d_in[7];
    const float* bk = (const float*)d_in[8];
    const float* Wv = (const float*)d_in[9];
    const float* bv = (const float*)d_in[10];
    const float* Wo = (const float*)d_in[11];
    const float* bo = (const float*)d_in[12];
    const float* l1g = (const float*)d_in[13];
    const float* l1b = (const float*)d_in[14];
    const float* l2g = (const float*)d_in[15];
    const float* l2b = (const float*)d_in[16];
    const float* W1 = (const float*)d_in[17];
    const float* b1 = (const float*)d_in[18];
    const float* W2 = (const float*)d_in[19];
    const float* b2 = (const float*)d_in[20];
    float* out = (float*)d_out;

    float *mem, *sE, *xb, *Kb, *Vb, *qb, *ob, *ao, *hb, *f1, *f2, *pl;
    cudaGetSymbolAddress((void**)&mem, g_mem);
    cudaGetSymbolAddress((void**)&sE, g_sE);
    cudaGetSymbolAddress((void**)&xb, g_x);
    cudaGetSymbolAddress((void**)&Kb, g_K);
    cudaGetSymbolAddress((void**)&Vb, g_V);
    cudaGetSymbolAddress((void**)&qb, g_q);
    cudaGetSymbolAddress((void**)&ob, g_o);
    cudaGetSymbolAddress((void**)&ao, g_ao);
    cudaGetSymbolAddress((void**)&hb, g_h);
    cudaGetSymbolAddress((void**)&f1, g_f1);
    cudaGetSymbolAddress((void**)&f2, g_f2);
    cudaGetSymbolAddress((void**)&pl, g_pl);

    static bool attr_done = false;
    if (!attr_done) {
        cudaFuncSetAttribute(tgemm_qkv, cudaFuncAttributeMaxDynamicSharedMemorySize, SMEM_BYTES);
        cudaFuncSetAttribute(tgemm_split<4, false, false>, cudaFuncAttributeMaxDynamicSharedMemorySize, SMEM_BYTES);
        cudaFuncSetAttribute(tgemm_split<1, true, true>, cudaFuncAttributeMaxDynamicSharedMemorySize, SMEM_BYTES);
        cudaFuncSetAttribute(tgemm_split<8, false, false>, cudaFuncAttributeMaxDynamicSharedMemorySize, SMEM_BYTES);
        attr_done = true;
    }

    pool_kernel<<<PP, 256>>>(sent, sidx, ss, ps, ns);

    dim3 gQKV(DD / 64, M2 / 64, 3);    // 288 blocks
    dim3 gWo(DD / 64, M2 / 64, 4);     // 384 blocks, 6 iters
    dim3 gW1(DFF / 64, M2 / 64, 1);    // 384 blocks, 24 iters
    dim3 gW2(DD / 64, M2 / 64, 8);     // 768 blocks, 12 iters

    tgemm_qkv<<<gQKV, 128, SMEM_BYTES>>>(mem, xb, Wk, Wv, Wq, bk, bv, bq, Kb, Vb, qb);
    attn_kernel<<<M2 * HH, 64>>>(qb, Kb, Vb, ob);
    tgemm_split<4, false, false><<<gWo, 128, SMEM_BYTES>>>(ob, Wo, nullptr, ao, M2, DD, DD);
    add_ln_kernel<4><<<M2, 256>>>(xb, ao, bo, l1g, l1b, hb);
    tgemm_split<1, true, true><<<gW1, 128, SMEM_BYTES>>>(hb, W1, b1, f1, M2, DD, DFF);
    tgemm_split<8, false, false><<<gW2, 128, SMEM_BYTES>>>(f1, W2, nullptr, f2, M2, DFF, DD);
    add_ln_loss_kernel<<<PP, 256>>>(hb, f2, b2, l2g, l2b, sE, pl);

    reduce_kernel<<<1, 256>>>(pl, out);
}

// round 6
// speedup vs baseline: 8.1098x; 1.1021x over previous
#include <cuda_runtime.h>
#include <cuda_bf16.h>
#include <math.h>

#define SS 512
#define DD 768
#define PP 256
#define HH 12
#define DH 64
#define DFF 3072
#define M2 (2*PP)
#define EPS_LN 1e-5f
#define EPS_TRIP 1e-6f

// GEMM tile: BM=64, BN=64, BK=32, 128 threads (4 warps, 2x2), warp tile 32x32, bf16 k16 MMA
#define SASB 40                 // bf16 stride (32 + 8 pad) -> conflict-free
#define ASZB (64 * SASB)        // bf16 elems per stage (A)
#define BSZB (64 * SASB)        // (B)
#define NSTAGE 3
#define QKVSZ ((size_t)M2 * DD)

typedef __nv_bfloat16 bf16;

// ---------------- scratch ----------------
__device__ float g_sE[PP * DD];
__device__ float g_x[M2 * DD];
__device__ bf16  g_xbf[M2 * DD];
__device__ bf16  g_membf[M2 * DD];
__device__ float g_qkvp[6 * M2 * DD];   // z = kh*3 + w; w: 0=K 1=V 2=Q
__device__ bf16  g_obf[M2 * DD];
__device__ float g_ao[4 * M2 * DD];
__device__ float g_h[M2 * DD];
__device__ bf16  g_hbf[M2 * DD];
__device__ bf16  g_f1bf[M2 * DFF];
__device__ float g_f2[8 * M2 * DD];
__device__ float g_pl[PP];
// transposed bf16 weights [N][K]
__device__ bf16 g_Tq[DD * DD];
__device__ bf16 g_Tk[DD * DD];
__device__ bf16 g_Tv[DD * DD];
__device__ bf16 g_To[DD * DD];
__device__ bf16 g_T1[DFF * DD];   // [3072][768]
__device__ bf16 g_T2[DD * DFF];   // [768][3072]

// ---------------- helpers ----------------
__device__ __forceinline__ void mma_bf16(float* c, const unsigned* a, unsigned b0, unsigned b1) {
    asm volatile(
        "mma.sync.aligned.m16n8k16.row.col.f32.bf16.bf16.f32 "
        "{%0,%1,%2,%3}, {%4,%5,%6,%7}, {%8,%9}, {%0,%1,%2,%3};"
        : "+f"(c[0]), "+f"(c[1]), "+f"(c[2]), "+f"(c[3])
        : "r"(a[0]), "r"(a[1]), "r"(a[2]), "r"(a[3]), "r"(b0), "r"(b1));
}

__device__ __forceinline__ void cp16(unsigned saddr, const void* gaddr) {
    asm volatile("cp.async.ca.shared.global [%0], [%1], 16;\n" :: "r"(saddr), "l"(gaddr));
}
__device__ __forceinline__ void cp_commit() {
    asm volatile("cp.async.commit_group;\n" ::);
}
__device__ __forceinline__ void cp_wait1() {
    asm volatile("cp.async.wait_group 1;\n" ::);
}

__device__ __forceinline__ float block_reduce_sum(float v, float* sh) {
    int lane = threadIdx.x & 31;
    int w = threadIdx.x >> 5;
    #pragma unroll
    for (int o = 16; o > 0; o >>= 1) v += __shfl_down_sync(0xffffffffu, v, o);
    __syncthreads();
    if (lane == 0) sh[w] = v;
    __syncthreads();
    int nw = blockDim.x >> 5;
    float r = (threadIdx.x < nw) ? sh[threadIdx.x] : 0.f;
    if (w == 0) {
        #pragma unroll
        for (int o = 16; o > 0; o >>= 1) r += __shfl_down_sync(0xffffffffu, r, o);
        if (lane == 0) sh[0] = r;
    }
    __syncthreads();
    return sh[0];
}

// ---------------- weight convert + transpose: [K][N] f32 -> [N][K] bf16 ----------------
__global__ __launch_bounds__(256) void convw_kernel(
    const float* __restrict__ Wq, const float* __restrict__ Wk,
    const float* __restrict__ Wv, const float* __restrict__ Wo,
    const float* __restrict__ W1, const float* __restrict__ W2) {
    int b = blockIdx.x;
    const float* src;
    bf16* dst;
    int K, N, t0;
    if (b < 2304) {
        int w = b / 576;
        t0 = b % 576;
        src = (w == 0) ? Wq : (w == 1) ? Wk : (w == 2) ? Wv : Wo;
        dst = (w == 0) ? g_Tq : (w == 1) ? g_Tk : (w == 2) ? g_Tv : g_To;
        K = DD; N = DD;
    } else if (b < 4608) {
        src = W1; dst = g_T1; K = DD; N = DFF; t0 = b - 2304;
    } else {
        src = W2; dst = g_T2; K = DFF; N = DD; t0 = b - 4608;
    }
    int ntn = N / 32;
    int tk = t0 / ntn, tn = t0 % ntn;
    __shared__ float tile[32][33];
    int tx = threadIdx.x & 31, ty = threadIdx.x >> 5;  // ty 0..7
    #pragma unroll
    for (int i = 0; i < 4; i++) {
        int k = tk * 32 + ty + i * 8;
        tile[ty + i * 8][tx] = src[(size_t)k * N + tn * 32 + tx];
    }
    __syncthreads();
    #pragma unroll
    for (int i = 0; i < 4; i++) {
        int n = tn * 32 + ty + i * 8;
        dst[(size_t)n * K + tk * 32 + tx] = __float2bfloat16_rn(tile[tx][ty + i * 8]);
    }
}

// ---------------- pooling ----------------
__global__ void pool_kernel(const float* __restrict__ se, const int* __restrict__ sidx,
                            const int* __restrict__ ss, const int* __restrict__ ps,
                            const int* __restrict__ ns) {
    int p = blockIdx.x;
    const float* base = se + (size_t)sidx[p] * SS * DD;
    int t = threadIdx.x;
    int s0 = ss[2 * p], s1 = ss[2 * p + 1];
    int p0 = ps[2 * p], p1 = ps[2 * p + 1];
    int n0 = ns[2 * p], n1 = ns[2 * p + 1];
    float inv_s = 1.0f / (float)(s1 - s0);
    float inv_p = 1.0f / (float)(p1 - p0);
    float inv_n = 1.0f / (float)(n1 - n0);
    #pragma unroll
    for (int i = 0; i < 3; i++) {
        int d = t + i * 256;
        float as = 0.f, ap = 0.f, an = 0.f;
        for (int r = s0; r < s1; r++) as += base[r * DD + d];
        for (int r = p0; r < p1; r++) ap += base[r * DD + d];
        for (int r = n0; r < n1; r++) an += base[r * DD + d];
        as *= inv_s; ap *= inv_p; an *= inv_n;
        g_sE[p * DD + d] = as;
        g_x[p * DD + d] = ap;
        g_x[(p + PP) * DD + d] = an;
        g_xbf[p * DD + d] = __float2bfloat16_rn(ap);
        g_xbf[(p + PP) * DD + d] = __float2bfloat16_rn(an);
        g_membf[p * 2 * DD + d] = __float2bfloat16_rn(base[d]);
        g_membf[p * 2 * DD + DD + d] = __float2bfloat16_rn(as);
    }
}

// ---------------- bf16 GEMM body ----------------
// A [M][K] bf16 row-major, Bt [N][K] bf16 row-major. C = A @ Bt^T (+bias, relu).
template <bool RELU, bool BIAS, bool OUTBF>
__device__ __forceinline__ void gemm_body(
    const bf16* __restrict__ A, const bf16* __restrict__ Bt,
    const float* __restrict__ bias, float* __restrict__ C, bf16* __restrict__ Cb,
    int K, int N, int kbeg, int kspan) {
    __shared__ bf16 sA[NSTAGE][ASZB];
    __shared__ bf16 sB[NSTAGE][BSZB];

    int tid = threadIdx.x;
    int lane = tid & 31;
    int wid = tid >> 5;
    int wm = wid >> 1;
    int wn = wid & 1;
    int q = lane >> 2;
    int r4 = lane & 3;
    int row0 = blockIdx.y * 64;
    int col0 = blockIdx.x * 64;

    float acc[2][4][4];
    #pragma unroll
    for (int i = 0; i < 2; i++)
        #pragma unroll
        for (int j = 0; j < 4; j++)
            #pragma unroll
            for (int k = 0; k < 4; k++) acc[i][j][k] = 0.f;

    unsigned uA = (unsigned)__cvta_generic_to_shared(&sA[0][0]);
    unsigned uB = (unsigned)__cvta_generic_to_shared(&sB[0][0]);

    int niter = kspan / 32;

    auto issue = [&](int it) {
        if (it < niter) {
            int k0 = kbeg + it * 32;
            int s = it % NSTAGE;
            unsigned dA = uA + s * (ASZB * 2);
            unsigned dB = uB + s * (BSZB * 2);
            #pragma unroll
            for (int i = 0; i < 2; i++) {
                int idx = tid + i * 128;
                int r = idx >> 2;             // 0..63
                int c = (idx & 3) * 8;        // 0,8,16,24
                cp16(dA + (r * SASB + c) * 2, A + (size_t)(row0 + r) * K + k0 + c);
                cp16(dB + (r * SASB + c) * 2, Bt + (size_t)(col0 + r) * K + k0 + c);
            }
        }
        cp_commit();
    };

    auto compute = [&](int it) {
        int s = it % NSTAGE;
        const bf16* cA = sA[s];
        const bf16* cB = sB[s];
        #pragma unroll
        for (int ks = 0; ks < 2; ks++) {
            int kk = ks * 16;
            unsigned a[2][4];
            #pragma unroll
            for (int mt = 0; mt < 2; mt++) {
                int rr = wm * 32 + mt * 16 + q;
                a[mt][0] = *(const unsigned*)&cA[rr * SASB + kk + 2 * r4];
                a[mt][1] = *(const unsigned*)&cA[(rr + 8) * SASB + kk + 2 * r4];
                a[mt][2] = *(const unsigned*)&cA[rr * SASB + kk + 2 * r4 + 8];
                a[mt][3] = *(const unsigned*)&cA[(rr + 8) * SASB + kk + 2 * r4 + 8];
            }
            #pragma unroll
            for (int nt = 0; nt < 4; nt++) {
                int cc = wn * 32 + nt * 8 + q;
                unsigned b0 = *(const unsigned*)&cB[cc * SASB + kk + 2 * r4];
                unsigned b1 = *(const unsigned*)&cB[cc * SASB + kk + 2 * r4 + 8];
                mma_bf16(acc[0][nt], a[0], b0, b1);
                mma_bf16(acc[1][nt], a[1], b0, b1);
            }
        }
    };

    issue(0);
    issue(1);
    for (int it = 0; it < niter; it++) {
        cp_wait1();
        __syncthreads();
        issue(it + 2);
        compute(it);
    }

    #pragma unroll
    for (int mt = 0; mt < 2; mt++) {
        int rr = row0 + wm * 32 + mt * 16 + q;
        #pragma unroll
        for (int nt = 0; nt < 4; nt++) {
            int cc = col0 + wn * 32 + nt * 8 + 2 * r4;
            float b0 = 0.f, b1 = 0.f;
            if (BIAS) { b0 = bias[cc]; b1 = bias[cc + 1]; }
            float v0 = acc[mt][nt][0] + b0;
            float v1 = acc[mt][nt][1] + b1;
            float v2 = acc[mt][nt][2] + b0;
            float v3 = acc[mt][nt][3] + b1;
            if (RELU) {
                v0 = fmaxf(v0, 0.f); v1 = fmaxf(v1, 0.f);
                v2 = fmaxf(v2, 0.f); v3 = fmaxf(v3, 0.f);
            }
            if (OUTBF) {
                __nv_bfloat162 w0, w1;
                w0.x = __float2bfloat16_rn(v0); w0.y = __float2bfloat16_rn(v1);
                w1.x = __float2bfloat16_rn(v2); w1.y = __float2bfloat16_rn(v3);
                *(__nv_bfloat162*)&Cb[(size_t)rr * N + cc] = w0;
                *(__nv_bfloat162*)&Cb[(size_t)(rr + 8) * N + cc] = w1;
            } else {
                *(float2*)&C[(size_t)rr * N + cc] = make_float2(v0, v1);
                *(float2*)&C[(size_t)(rr + 8) * N + cc] = make_float2(v2, v3);
            }
        }
    }
}

// ---------------- QKV GEMM (grid.z = 6: kh*3 + w) ----------------
__global__ __launch_bounds__(128) void tgemm_qkv(float* __restrict__ parts) {
    int z = blockIdx.z;
    int w = z % 3;
    int kh = z / 3;
    const bf16* A = (w == 2) ? g_xbf : g_membf;
    const bf16* B = (w == 0) ? g_Tk : ((w == 1) ? g_Tv : g_Tq);
    float* C = parts + (size_t)z * QKVSZ;
    gemm_body<false, false, false>(A, B, nullptr, C, nullptr, DD, DD, kh * 384, 384);
}

// ---------------- split-K GEMM ----------------
template <int SPLITK, bool RELU, bool BIAS, bool OUTBF>
__global__ __launch_bounds__(128) void tgemm_split(
    const bf16* __restrict__ A, const bf16* __restrict__ Bt,
    const float* __restrict__ bias, float* __restrict__ C, bf16* __restrict__ Cb,
    int M, int K, int N) {
    int z = blockIdx.z;
    int kspan = K / SPLITK;
    float* Cz = OUTBF ? C : (C + (size_t)z * M * N);
    gemm_body<RELU, BIAS, OUTBF>(A, Bt, bias, Cz, Cb, K, N, z * kspan, kspan);
}

// ---------------- 2-slot attention (combines QKV split-K parts + bias) ----------------
__global__ void attn_kernel(const float* __restrict__ parts,
                            const float* __restrict__ bq, const float* __restrict__ bk,
                            const float* __restrict__ bv, bf16* __restrict__ obf) {
    const float* kp0 = parts;
    const float* vp0 = parts + QKVSZ;
    const float* qp0 = parts + 2 * QKVSZ;
    const float* kp1 = parts + 3 * QKVSZ;
    const float* vp1 = parts + 4 * QKVSZ;
    const float* qp1 = parts + 5 * QKVSZ;
    int rh = blockIdx.x;
    int r = rh / HH;
    int h = rh % HH;
    int p = r & (PP - 1);
    int d = threadIdx.x;
    int hd = h * DH + d;
    size_t qoff = (size_t)r * DD + hd;
    size_t k0off = (size_t)p * 2 * DD + hd;
    float qd = qp0[qoff] + qp1[qoff] + bq[hd];
    float k0v = kp0[k0off] + kp1[k0off] + bk[hd];
    float k1v = kp0[k0off + DD] + kp1[k0off + DD] + bk[hd];
    float s0 = qd * k0v;
    float s1 = qd * k1v;
    __shared__ float sh[4];
    #pragma unroll
    for (int off = 16; off > 0; off >>= 1) {
        s0 += __shfl_down_sync(0xffffffffu, s0, off);
        s1 += __shfl_down_sync(0xffffffffu, s1, off);
    }
    int w = threadIdx.x >> 5;
    if ((threadIdx.x & 31) == 0) { sh[w * 2] = s0; sh[w * 2 + 1] = s1; }
    __syncthreads();
    s0 = (sh[0] + sh[2]) * 0.125f;
    s1 = (sh[1] + sh[3]) * 0.125f;
    float m = fmaxf(s0, s1);
    float e0 = expf(s0 - m), e1 = expf(s1 - m);
    float inv = 1.f / (e0 + e1);
    float v0 = vp0[k0off] + vp1[k0off] + bv[hd];
    float v1 = vp0[k0off + DD] + vp1[k0off + DD] + bv[hd];
    obf[qoff] = __float2bfloat16_rn((e0 * inv) * v0 + (e1 * inv) * v1);
}

// ---------------- residual + split-K combine + bias + LayerNorm (f32 + bf16 out) ----------------
template <int NPARTS>
__global__ void add_ln_kernel(const float* __restrict__ x, const float* __restrict__ parts,
                              const float* __restrict__ bias,
                              const float* __restrict__ g, const float* __restrict__ b,
                              float* __restrict__ out, bf16* __restrict__ outbf) {
    int p = blockIdx.x;
    int t = threadIdx.x;
    __shared__ float sh[8];
    float v[3];
    float s = 0.f, s2 = 0.f;
    #pragma unroll
    for (int i = 0; i < 3; i++) {
        int d = t + i * 256;
        float acc = x[(size_t)p * DD + d] + bias[d];
        #pragma unroll
        for (int k = 0; k < NPARTS; k++)
            acc += parts[(size_t)k * M2 * DD + (size_t)p * DD + d];
        v[i] = acc;
        s += acc;
        s2 += acc * acc;
    }
    float sum = block_reduce_sum(s, sh);
    float sumsq = block_reduce_sum(s2, sh);
    float mean = sum * (1.0f / DD);
    float var = sumsq * (1.0f / DD) - mean * mean;
    float rstd = rsqrtf(var + EPS_LN);
    #pragma unroll
    for (int i = 0; i < 3; i++) {
        int d = t + i * 256;
        float o = (v[i] - mean) * rstd * g[d] + b[d];
        out[(size_t)p * DD + d] = o;
        outbf[(size_t)p * DD + d] = __float2bfloat16_rn(o);
    }
}

// ---------------- fused: 2nd add+LN (8 parts) + triplet loss ----------------
__global__ void add_ln_loss_kernel(const float* __restrict__ hb, const float* __restrict__ parts,
                                   const float* __restrict__ bias,
                                   const float* __restrict__ g, const float* __restrict__ b,
                                   const float* __restrict__ sE, float* __restrict__ pl) {
    int p = blockIdx.x;
    int t = threadIdx.x;
    __shared__ float sh[8];
    float vp[3], vn[3];
    float sp = 0.f, sp2 = 0.f, sn = 0.f, sn2 = 0.f;
    #pragma unroll
    for (int i = 0; i < 3; i++) {
        int d = t + i * 256;
        float ap = hb[(size_t)p * DD + d] + bias[d];
        float an = hb[(size_t)(p + PP) * DD + d] + bias[d];
        #pragma unroll
        for (int k = 0; k < 8; k++) {
            ap += parts[(size_t)k * M2 * DD + (size_t)p * DD + d];
            an += parts[(size_t)k * M2 * DD + (size_t)(p + PP) * DD + d];
        }
        vp[i] = ap; vn[i] = an;
        sp += ap; sp2 += ap * ap;
        sn += an; sn2 += an * an;
    }
    float sump = block_reduce_sum(sp, sh);
    float sumsqp = block_reduce_sum(sp2, sh);
    float sumn = block_reduce_sum(sn, sh);
    float sumsqn = block_reduce_sum(sn2, sh);
    float meanp = sump * (1.0f / DD);
    float rstdp = rsqrtf(sumsqp * (1.0f / DD) - meanp * meanp + EPS_LN);
    float meann = sumn * (1.0f / DD);
    float rstdn = rsqrtf(sumsqn * (1.0f / DD) - meann * meann + EPS_LN);
    float dp = 0.f, dn = 0.f;
    #pragma unroll
    for (int i = 0; i < 3; i++) {
        int d = t + i * 256;
        float attp = (vp[i] - meanp) * rstdp * g[d] + b[d];
        float attn = (vn[i] - meann) * rstdn * g[d] + b[d];
        float e = sE[(size_t)p * DD + d];
        float a = e - attp + EPS_TRIP;
        float c = e - attn + EPS_TRIP;
        dp += a * a;
        dn += c * c;
    }
    float DP = block_reduce_sum(dp, sh);
    float DN = block_reduce_sum(dn, sh);
    if (t == 0) pl[p] = fmaxf(sqrtf(DP) - sqrtf(DN) + 1.0f, 0.f);
}

__global__ void reduce_kernel(const float* __restrict__ pl, float* __restrict__ out) {
    int t = threadIdx.x;
    __shared__ float sh[8];
    float s = block_reduce_sum(pl[t], sh);
    if (t == 0) out[0] = s * (1.0f / PP);
}

// ---------------- host launch ----------------
extern "C" void kernel_launch(void* const* d_in, const int* in_sizes, int n_in,
                              void* d_out, int out_size) {
    const float* sent = (const float*)d_in[0];
    const int* sidx = (const int*)d_in[1];
    const int* ss = (const int*)d_in[2];
    const int* ps = (const int*)d_in[3];
    const int* ns = (const int*)d_in[4];
    const float* Wq = (const float*)d_in[5];
    const float* bq = (const float*)d_in[6];
    const float* Wk = (const float*)d_in[7];
    const float* bk = (const float*)d_in[8];
    const float* Wv = (const float*)d_in[9];
    const float* bv = (const float*)d_in[10];
    const float* Wo = (const float*)d_in[11];
    const float* bo = (const float*)d_in[12];
    const float* l1g = (const float*)d_in[13];
    const float* l1b = (const float*)d_in[14];
    const float* l2g = (const float*)d_in[15];
    const float* l2b = (const float*)d_in[16];
    const float* W1 = (const float*)d_in[17];
    const float* b1 = (const float*)d_in[18];
    const float* W2 = (const float*)d_in[19];
    const float* b2 = (const float*)d_in[20];
    float* out = (float*)d_out;

    float *sE, *xb, *qkvp, *ao, *hb, *f2, *pl;
    bf16 *obf, *hbf, *f1bf, *To, *T1, *T2;
    cudaGetSymbolAddress((void**)&sE, g_sE);
    cudaGetSymbolAddress((void**)&xb, g_x);
    cudaGetSymbolAddress((void**)&qkvp, g_qkvp);
    cudaGetSymbolAddress((void**)&ao, g_ao);
    cudaGetSymbolAddress((void**)&hb, g_h);
    cudaGetSymbolAddress((void**)&f2, g_f2);
    cudaGetSymbolAddress((void**)&pl, g_pl);
    cudaGetSymbolAddress((void**)&obf, g_obf);
    cudaGetSymbolAddress((void**)&hbf, g_hbf);
    cudaGetSymbolAddress((void**)&f1bf, g_f1bf);
    cudaGetSymbolAddress((void**)&To, g_To);
    cudaGetSymbolAddress((void**)&T1, g_T1);
    cudaGetSymbolAddress((void**)&T2, g_T2);

    convw_kernel<<<6912, 256>>>(Wq, Wk, Wv, Wo, W1, W2);
    pool_kernel<<<PP, 256>>>(sent, sidx, ss, ps, ns);

    dim3 gQKV(DD / 64, M2 / 64, 6);    // 576 blocks, 12 iters
    dim3 gWo(DD / 64, M2 / 64, 4);     // 384 blocks, 6 iters
    dim3 gW1(DFF / 64, M2 / 64, 1);    // 384 blocks, 24 iters
    dim3 gW2(DD / 64, M2 / 64, 8);     // 768 blocks, 12 iters

    tgemm_qkv<<<gQKV, 128>>>(qkvp);
    attn_kernel<<<M2 * HH, 64>>>(qkvp, bq, bk, bv, obf);
    tgemm_split<4, false, false, false><<<gWo, 128>>>(obf, To, nullptr, ao, nullptr, M2, DD, DD);
    add_ln_kernel<4><<<M2, 256>>>(xb, ao, bo, l1g, l1b, hb, hbf);
    tgemm_split<1, true, true, true><<<gW1, 128>>>(hbf, T1, b1, nullptr, f1bf, M2, DD, DFF);
    tgemm_split<8, false, false, false><<<gW2, 128>>>(f1bf, T2, nullptr, f2, nullptr, M2, DFF, DD);
    add_ln_loss_kernel<<<PP, 256>>>(hb, f2, b2, l2g, l2b, sE, pl);

    reduce_kernel<<<1, 256>>>(pl, out);
}